// round 3
// baseline (speedup 1.0000x reference)
#include <cuda_runtime.h>
#include <math.h>

#define Bdim 2
#define Nseq 1536
#define Dmod 1024
#define Hn   16
#define DHd  64
#define SCALE 0.125f
#define ROWS (Bdim * Nseq)          // 3072
#define OUT_ELEMS ((size_t)ROWS * Dmod)  // 3145728

// scratch (no cudaMalloc allowed)
__device__ float g_Q [ROWS * Dmod];
__device__ float g_K [ROWS * Dmod];
__device__ float g_V [ROWS * Dmod];
__device__ float g_H1[ROWS * Dmod];
__device__ float g_AT[ROWS * Dmod];
__device__ float g_gate[ROWS];

// ---------------------------------------------------------------------------
// Generic tiled fp32 GEMM: C[M,N] = A[M,K] @ W[K,N] + bias, optional exact GELU
// 64x64 tile, k-tile 16, 256 threads, 4x4 per thread.
// ---------------------------------------------------------------------------
__global__ void __launch_bounds__(256)
gemm_bias_act(const float* __restrict__ A,
              const float* __restrict__ W,
              const float* __restrict__ bias,
              float* __restrict__ C,
              int M, int N, int K, int act)
{
    __shared__ float As[16][64];   // transposed: As[k][m]
    __shared__ float Ws[16][64];   // Ws[k][n]

    const int tid = threadIdx.x;
    const int tx = tid & 15;
    const int ty = tid >> 4;
    const int m0 = blockIdx.y * 64;
    const int n0 = blockIdx.x * 64;

    const int ar = tid >> 2;          // 0..63  (A tile row)
    const int ac = (tid & 3) << 2;    // 0,4,8,12 (A tile col, float4)
    const int wr = tid >> 4;          // 0..15  (W tile row)
    const int wc = (tid & 15) << 2;   // 0..60  (W tile col, float4)

    float acc[4][4] = {};

    for (int k0 = 0; k0 < K; k0 += 16) {
        float4 av = *(const float4*)(A + (size_t)(m0 + ar) * K + k0 + ac);
        float4 wv = *(const float4*)(W + (size_t)(k0 + wr) * N + n0 + wc);
        __syncthreads();
        As[ac + 0][ar] = av.x;
        As[ac + 1][ar] = av.y;
        As[ac + 2][ar] = av.z;
        As[ac + 3][ar] = av.w;
        *(float4*)&Ws[wr][wc] = wv;
        __syncthreads();

#pragma unroll
        for (int kk = 0; kk < 16; kk++) {
            float4 a4 = *(const float4*)&As[kk][ty << 2];
            float4 b4 = *(const float4*)&Ws[kk][tx << 2];
            float av_[4] = {a4.x, a4.y, a4.z, a4.w};
            float bv_[4] = {b4.x, b4.y, b4.z, b4.w};
#pragma unroll
            for (int i = 0; i < 4; i++)
#pragma unroll
                for (int j = 0; j < 4; j++)
                    acc[i][j] += av_[i] * bv_[j];
        }
    }

#pragma unroll
    for (int i = 0; i < 4; i++) {
        int m = m0 + (ty << 2) + i;
#pragma unroll
        for (int j = 0; j < 4; j++) {
            int n = n0 + (tx << 2) + j;
            float v = acc[i][j] + bias[n];
            if (act == 1)
                v = 0.5f * v * (1.0f + erff(v * 0.70710678118654752f));
            C[(size_t)m * N + n] = v;
        }
    }
}

// ---------------------------------------------------------------------------
// gate[row] = sigmoid(dot(H1[row,:], Wg2) + bg2)
// ---------------------------------------------------------------------------
__global__ void __launch_bounds__(256)
gate_kernel(const float* __restrict__ H1,
            const float* __restrict__ Wg2,
            const float* __restrict__ bg2,
            float* __restrict__ gate)
{
    __shared__ float red[8];
    const int row = blockIdx.x;
    const float* hp = H1 + (size_t)row * Dmod;
    float loc = 0.f;
    for (int k = threadIdx.x; k < Dmod; k += blockDim.x)
        loc += hp[k] * Wg2[k];
#pragma unroll
    for (int o = 16; o > 0; o >>= 1)
        loc += __shfl_xor_sync(0xffffffffu, loc, o);
    const int w = threadIdx.x >> 5;
    if ((threadIdx.x & 31) == 0) red[w] = loc;
    __syncthreads();
    if (threadIdx.x == 0) {
        float s = 0.f;
        for (int i = 0; i < 8; i++) s += red[i];
        gate[row] = 1.f / (1.f + expf(-(s + bg2[0])));
    }
}

// ---------------------------------------------------------------------------
// block reductions for 128 threads (4 warps)
// ---------------------------------------------------------------------------
__device__ __forceinline__ float bred_max(float v, float* red)
{
#pragma unroll
    for (int o = 16; o > 0; o >>= 1)
        v = fmaxf(v, __shfl_xor_sync(0xffffffffu, v, o));
    if ((threadIdx.x & 31) == 0) red[threadIdx.x >> 5] = v;
    __syncthreads();
    float r = fmaxf(fmaxf(red[0], red[1]), fmaxf(red[2], red[3]));
    __syncthreads();
    return r;
}

__device__ __forceinline__ float bred_sum(float v, float* red)
{
#pragma unroll
    for (int o = 16; o > 0; o >>= 1)
        v += __shfl_xor_sync(0xffffffffu, v, o);
    if ((threadIdx.x & 31) == 0) red[threadIdx.x >> 5] = v;
    __syncthreads();
    float r = red[0] + red[1] + red[2] + red[3];
    __syncthreads();
    return r;
}

// ---------------------------------------------------------------------------
// One block per (b, h, q) query row. 128 threads.
//   pass 1: scores  s_j = (q . k_j) * SCALE   (causal: j <= q)
//   softmax + exact entropy with log(p + 1e-6)
//   pass 2: out_d = gate * sum_j p_j V[j][d]
// ---------------------------------------------------------------------------
#define KV_STRIDE 65   // padded row stride (bank-conflict-free)

__global__ void __launch_bounds__(128)
attn_kernel(const float* __restrict__ gate,
            float* __restrict__ entropy_out)
{
    __shared__ float qs[64];
    __shared__ float sc[Nseq];
    __shared__ float kv[128 * KV_STRIDE];
    __shared__ float red[4];
    __shared__ float red2[64];

    const int bid = blockIdx.x;
    const int q = bid % Nseq;
    const int h = (bid / Nseq) % Hn;
    const int b = bid / (Nseq * Hn);
    const int tid = threadIdx.x;

    const size_t headoff = (size_t)b * Nseq * Dmod + (size_t)h * DHd;

    if (tid < 64)
        qs[tid] = g_Q[headoff + (size_t)q * Dmod + tid];
    const int nk = q + 1;

    // ---- pass 1: scores ----
    for (int t0 = 0; t0 < nk; t0 += 128) {
        const int tn = min(128, nk - t0);
        __syncthreads();
        for (int idx = tid; idx < tn * 16; idx += 128) {
            int r = idx >> 4;
            int c = (idx & 15) << 2;
            float4 v = *(const float4*)(g_K + headoff + (size_t)(t0 + r) * Dmod + c);
            int sb = r * KV_STRIDE + c;
            kv[sb + 0] = v.x; kv[sb + 1] = v.y; kv[sb + 2] = v.z; kv[sb + 3] = v.w;
        }
        __syncthreads();
        for (int j = tid; j < tn; j += 128) {
            float s = 0.f;
            const float* kr = &kv[j * KV_STRIDE];
#pragma unroll
            for (int d = 0; d < 64; d++)
                s += qs[d] * kr[d];
            sc[t0 + j] = s * SCALE;
        }
    }
    __syncthreads();

    // ---- softmax ----
    float m = -1e30f;
    for (int j = tid; j < nk; j += 128) m = fmaxf(m, sc[j]);
    m = bred_max(m, red);

    float lsum = 0.f;
    for (int j = tid; j < nk; j += 128) {
        float e = expf(sc[j] - m);
        sc[j] = e;
        lsum += e;
    }
    const float l = bred_sum(lsum, red);
    const float inv_l = 1.f / l;

    // ---- entropy: -(sum p * log(p + 1e-6)) ----
    float eloc = 0.f;
    for (int j = tid; j < nk; j += 128) {
        float p = sc[j] * inv_l;
        eloc += p * logf(p + 1e-6f);
    }
    const float esum = bred_sum(eloc, red);
    if (tid == 0)
        entropy_out[((size_t)b * Hn + h) * Nseq + q] = -esum;

    // ---- pass 2: out = (p @ V) * inv_l * gate ----
    const int d = tid & 63;
    const int part = tid >> 6;
    float accv = 0.f;
    for (int t0 = 0; t0 < nk; t0 += 128) {
        const int tn = min(128, nk - t0);
        __syncthreads();
        for (int idx = tid; idx < tn * 16; idx += 128) {
            int r = idx >> 4;
            int c = (idx & 15) << 2;
            float4 v = *(const float4*)(g_V + headoff + (size_t)(t0 + r) * Dmod + c);
            int sb = r * KV_STRIDE + c;
            kv[sb + 0] = v.x; kv[sb + 1] = v.y; kv[sb + 2] = v.z; kv[sb + 3] = v.w;
        }
        __syncthreads();
        for (int jl = part; jl < tn; jl += 2)
            accv += sc[t0 + jl] * kv[jl * KV_STRIDE + d];
    }
    __syncthreads();
    if (part == 1) red2[d] = accv;
    __syncthreads();
    if (part == 0) {
        float tot = (accv + red2[d]) * inv_l * gate[b * Nseq + q];
        g_AT[headoff + (size_t)q * Dmod + d] = tot;
    }
}

// ---------------------------------------------------------------------------
extern "C" void kernel_launch(void* const* d_in, const int* in_sizes, int n_in,
                              void* d_out, int out_size)
{
    const float* x   = (const float*)d_in[0];
    // d_in[1] = attn_bias (exact causal prior; handled analytically by loop bound)
    const float* Wq  = (const float*)d_in[2];
    const float* bq  = (const float*)d_in[3];
    const float* Wk  = (const float*)d_in[4];
    const float* bk  = (const float*)d_in[5];
    const float* Wv  = (const float*)d_in[6];
    const float* bv  = (const float*)d_in[7];
    const float* Wg1 = (const float*)d_in[8];
    const float* bg1 = (const float*)d_in[9];
    const float* Wg2 = (const float*)d_in[10];
    const float* bg2 = (const float*)d_in[11];
    const float* Wo  = (const float*)d_in[12];
    const float* bo  = (const float*)d_in[13];

    float* out = (float*)d_out;

    float *Qp, *Kp, *Vp, *H1p, *ATp, *gp;
    cudaGetSymbolAddress((void**)&Qp,  g_Q);
    cudaGetSymbolAddress((void**)&Kp,  g_K);
    cudaGetSymbolAddress((void**)&Vp,  g_V);
    cudaGetSymbolAddress((void**)&H1p, g_H1);
    cudaGetSymbolAddress((void**)&ATp, g_AT);
    cudaGetSymbolAddress((void**)&gp,  g_gate);

    dim3 gg(Dmod / 64, ROWS / 64);   // (16, 48)
    dim3 gb(256);

    gemm_bias_act<<<gg, gb>>>(x, Wq,  bq,  Qp,  ROWS, Dmod, Dmod, 0);
    gemm_bias_act<<<gg, gb>>>(x, Wk,  bk,  Kp,  ROWS, Dmod, Dmod, 0);
    gemm_bias_act<<<gg, gb>>>(x, Wv,  bv,  Vp,  ROWS, Dmod, Dmod, 0);
    gemm_bias_act<<<gg, gb>>>(x, Wg1, bg1, H1p, ROWS, Dmod, Dmod, 1);

    gate_kernel<<<ROWS, 256>>>(H1p, Wg2, bg2, gp);

    attn_kernel<<<Bdim * Hn * Nseq, 128>>>(gp, out + OUT_ELEMS);

    gemm_bias_act<<<gg, gb>>>(ATp, Wo, bo, out, ROWS, Dmod, Dmod, 0);
}

// round 4
// speedup vs baseline: 4.7807x; 4.7807x over previous
#include <cuda_runtime.h>
#include <math.h>

#define Bdim 2
#define Nseq 1536
#define Dmod 1024
#define Hn   16
#define DHd  64
#define SCALE 0.125f
#define ROWS (Bdim * Nseq)               // 3072
#define OUT_ELEMS ((size_t)ROWS * Dmod)  // 3145728
#define BH (Bdim * Hn)                   // 32

// scratch (no cudaMalloc allowed)
__device__ float g_Q [ROWS * Dmod];
__device__ float g_K [ROWS * Dmod];
__device__ float g_V [ROWS * Dmod];
__device__ float g_H1[ROWS * Dmod];
__device__ float g_AT[ROWS * Dmod];
__device__ float g_gate[ROWS];
__device__ float g_m[BH * Nseq];
__device__ float g_l[BH * Nseq];
__device__ float g_S[(size_t)BH * Nseq * Nseq];   // raw scores, 302 MB

// ---------------------------------------------------------------------------
// packed f32x2 helpers (sm_103a FFMA2 path)
// ---------------------------------------------------------------------------
__device__ __forceinline__ unsigned long long pk2(float lo, float hi) {
    unsigned long long r;
    asm("mov.b64 %0, {%1,%2};" : "=l"(r) : "f"(lo), "f"(hi));
    return r;
}
__device__ __forceinline__ void upk2(unsigned long long v, float& lo, float& hi) {
    asm("mov.b64 {%0,%1}, %2;" : "=f"(lo), "=f"(hi) : "l"(v));
}
#define FMA2(d, a, b) asm("fma.rn.f32x2 %0, %1, %2, %0;" : "+l"(d) : "l"(a), "l"(b))

// ---------------------------------------------------------------------------
// 128x128 tiled fp32 GEMM with FFMA2, 256 threads, 8x8 per thread.
// Handles up to 4 weight segments (for fused QKV+G1: grid.x = 32, seg = bx>>3).
// C[seg] = A @ W[seg] + bias[seg], exact-erf GELU on segment == actseg.
// ---------------------------------------------------------------------------
__global__ void __launch_bounds__(256)
gemm128(const float* __restrict__ A,
        const float* __restrict__ W0, const float* __restrict__ W1,
        const float* __restrict__ W2, const float* __restrict__ W3,
        const float* __restrict__ Bi0, const float* __restrict__ Bi1,
        const float* __restrict__ Bi2, const float* __restrict__ Bi3,
        float* __restrict__ C0, float* __restrict__ C1,
        float* __restrict__ C2, float* __restrict__ C3,
        int actseg)
{
    __shared__ float Ast[16 * 132];   // transposed A tile [k][m]
    __shared__ float Ws [16 * 132];   // W tile [k][n]

    const int seg = blockIdx.x >> 3;
    const float* W  = (seg == 0) ? W0  : (seg == 1) ? W1  : (seg == 2) ? W2  : W3;
    const float* Bp = (seg == 0) ? Bi0 : (seg == 1) ? Bi1 : (seg == 2) ? Bi2 : Bi3;
    float*       C  = (seg == 0) ? C0  : (seg == 1) ? C1  : (seg == 2) ? C2  : C3;
    const bool act = (seg == actseg);

    const int n0 = (blockIdx.x & 7) << 7;
    const int m0 = blockIdx.y << 7;
    const int tid = threadIdx.x;
    const int tx = tid & 15, ty = tid >> 4;
    const int r0 = ty << 3, c0 = tx << 3;

    unsigned long long acc[8][4];
#pragma unroll
    for (int i = 0; i < 8; i++)
#pragma unroll
        for (int j = 0; j < 4; j++) acc[i][j] = 0ull;

    for (int k0 = 0; k0 < 1024; k0 += 16) {
        __syncthreads();
        int i = tid;
#pragma unroll
        for (int p = 0; p < 2; p++, i += 256) {   // A: 128x16, transposed store
            int r = i >> 2, c = (i & 3) << 2;
            float4 v = *(const float4*)(A + (size_t)(m0 + r) * 1024 + k0 + c);
            Ast[(c + 0) * 132 + r] = v.x;
            Ast[(c + 1) * 132 + r] = v.y;
            Ast[(c + 2) * 132 + r] = v.z;
            Ast[(c + 3) * 132 + r] = v.w;
        }
        i = tid;
#pragma unroll
        for (int p = 0; p < 2; p++, i += 256) {   // W: 16x128, direct
            int r = i >> 5, c = (i & 31) << 2;
            *(float4*)(Ws + r * 132 + c) =
                *(const float4*)(W + (size_t)(k0 + r) * 1024 + n0 + c);
        }
        __syncthreads();

#pragma unroll
        for (int kk = 0; kk < 16; kk++) {
            float4 a0 = *(const float4*)(Ast + kk * 132 + r0);
            float4 a1 = *(const float4*)(Ast + kk * 132 + r0 + 4);
            float4 b0 = *(const float4*)(Ws  + kk * 132 + c0);
            float4 b1 = *(const float4*)(Ws  + kk * 132 + c0 + 4);
            unsigned long long bp[4] = { pk2(b0.x, b0.y), pk2(b0.z, b0.w),
                                         pk2(b1.x, b1.y), pk2(b1.z, b1.w) };
            float av[8] = {a0.x, a0.y, a0.z, a0.w, a1.x, a1.y, a1.z, a1.w};
#pragma unroll
            for (int ii = 0; ii < 8; ii++) {
                unsigned long long ap = pk2(av[ii], av[ii]);
#pragma unroll
                for (int jj = 0; jj < 4; jj++) FMA2(acc[ii][jj], ap, bp[jj]);
            }
        }
    }

#pragma unroll
    for (int ii = 0; ii < 8; ii++) {
        float o[8];
#pragma unroll
        for (int jj = 0; jj < 4; jj++) upk2(acc[ii][jj], o[2 * jj], o[2 * jj + 1]);
#pragma unroll
        for (int jj = 0; jj < 8; jj++) {
            float v = o[jj] + Bp[n0 + c0 + jj];
            if (act) v = 0.5f * v * (1.0f + erff(v * 0.70710678118654752f));
            o[jj] = v;
        }
        float* cp = C + (size_t)(m0 + r0 + ii) * 1024 + n0 + c0;
        *(float4*)cp       = make_float4(o[0], o[1], o[2], o[3]);
        *(float4*)(cp + 4) = make_float4(o[4], o[5], o[6], o[7]);
    }
}

// ---------------------------------------------------------------------------
// gate[row] = sigmoid(dot(H1[row,:], Wg2) + bg2)
// ---------------------------------------------------------------------------
__global__ void __launch_bounds__(256)
gate_kernel(const float* __restrict__ H1,
            const float* __restrict__ Wg2,
            const float* __restrict__ bg2,
            float* __restrict__ gate)
{
    __shared__ float red[8];
    const int row = blockIdx.x;
    const float* hp = H1 + (size_t)row * Dmod;
    float loc = 0.f;
    for (int k = threadIdx.x; k < Dmod; k += blockDim.x)
        loc += hp[k] * Wg2[k];
#pragma unroll
    for (int o = 16; o > 0; o >>= 1)
        loc += __shfl_xor_sync(0xffffffffu, loc, o);
    if ((threadIdx.x & 31) == 0) red[threadIdx.x >> 5] = loc;
    __syncthreads();
    if (threadIdx.x == 0) {
        float s = 0.f;
        for (int i = 0; i < 8; i++) s += red[i];
        gate[row] = 1.f / (1.f + __expf(-(s + bg2[0])));
    }
}

// ---------------------------------------------------------------------------
// Flash attention: one CTA per (b, h, 128-query tile). 256 threads, 16x16 grid,
// each thread owns 8 query rows x 4 key cols of S and 8 rows x 4 dims of O.
// Online softmax; raw scores spilled to g_S for the exact-entropy pass.
// ---------------------------------------------------------------------------
#define QPAD 132
#define KPAD 68
#define FLASH_SMEM ((64 * QPAD + 64 * KPAD + 64 * KPAD + 64 * QPAD) * 4)  // 102400 B

__global__ void __launch_bounds__(256)
flash_kernel()
{
    extern __shared__ float smf[];
    float* Qst = smf;                   // [d=64][q=128] transposed, *SCALE folded
    float* Kst = Qst + 64 * QPAD;       // [d=64][k=64]  transposed
    float* Vs  = Kst + 64 * KPAD;       // [k=64][d=64]
    float* Pst = Vs  + 64 * KPAD;       // [k=64][q=128] transposed probs

    const int qt = blockIdx.x;
    const int bh = blockIdx.y;
    const int b = bh >> 4, h = bh & 15;
    const int qg0 = qt << 7;
    const int tid = threadIdx.x;
    const int tx = tid & 15, ty = tid >> 4;
    const int r0 = ty << 3, c0 = tx << 2;
    const size_t base = (size_t)b * Nseq * Dmod + (size_t)h * DHd;

    // load Q tile (transposed, pre-scaled)
    for (int i = tid; i < 128 * 16; i += 256) {
        int r = i >> 4, c = (i & 15) << 2;
        float4 v = *(const float4*)(g_Q + base + (size_t)(qg0 + r) * Dmod + c);
        Qst[(c + 0) * QPAD + r] = v.x * SCALE;
        Qst[(c + 1) * QPAD + r] = v.y * SCALE;
        Qst[(c + 2) * QPAD + r] = v.z * SCALE;
        Qst[(c + 3) * QPAD + r] = v.w * SCALE;
    }

    float m[8], l[8], acc[8][4];
#pragma unroll
    for (int i = 0; i < 8; i++) {
        m[i] = -1e30f; l[i] = 0.f;
#pragma unroll
        for (int j = 0; j < 4; j++) acc[i][j] = 0.f;
    }

    const size_t sbase = (size_t)bh * Nseq * Nseq;
    const int ktiles = 2 * qt + 2;

    for (int kt = 0; kt < ktiles; kt++) {
        const int k0 = kt << 6;
        __syncthreads();
        // stage K (transposed) and V (natural)
        for (int i = tid; i < 64 * 16; i += 256) {
            int r = i >> 4, c = (i & 15) << 2;
            float4 kv = *(const float4*)(g_K + base + (size_t)(k0 + r) * Dmod + c);
            Kst[(c + 0) * KPAD + r] = kv.x;
            Kst[(c + 1) * KPAD + r] = kv.y;
            Kst[(c + 2) * KPAD + r] = kv.z;
            Kst[(c + 3) * KPAD + r] = kv.w;
            *(float4*)(Vs + r * KPAD + c) =
                *(const float4*)(g_V + base + (size_t)(k0 + r) * Dmod + c);
        }
        __syncthreads();

        // S = Q K^T  (8x4 per thread)
        float s[8][4];
#pragma unroll
        for (int i = 0; i < 8; i++)
#pragma unroll
            for (int j = 0; j < 4; j++) s[i][j] = 0.f;
        for (int d = 0; d < 64; d++) {
            float4 qa = *(const float4*)(Qst + d * QPAD + r0);
            float4 qb = *(const float4*)(Qst + d * QPAD + r0 + 4);
            float4 kk = *(const float4*)(Kst + d * KPAD + c0);
            float qv[8] = {qa.x, qa.y, qa.z, qa.w, qb.x, qb.y, qb.z, qb.w};
            float kv[4] = {kk.x, kk.y, kk.z, kk.w};
#pragma unroll
            for (int i = 0; i < 8; i++)
#pragma unroll
                for (int j = 0; j < 4; j++) s[i][j] += qv[i] * kv[j];
        }

        // spill raw scores for the entropy pass
#pragma unroll
        for (int i = 0; i < 8; i++)
            *(float4*)(g_S + sbase + (size_t)(qg0 + r0 + i) * Nseq + k0 + c0) =
                make_float4(s[i][0], s[i][1], s[i][2], s[i][3]);

        // causal mask (only the two diagonal tiles can mask)
        if (kt >= 2 * qt) {
#pragma unroll
            for (int i = 0; i < 8; i++)
#pragma unroll
                for (int j = 0; j < 4; j++)
                    if (k0 + c0 + j > qg0 + r0 + i) s[i][j] = -1e30f;
        }

        // online softmax update
#pragma unroll
        for (int i = 0; i < 8; i++) {
            float mt = fmaxf(fmaxf(s[i][0], s[i][1]), fmaxf(s[i][2], s[i][3]));
#pragma unroll
            for (int o = 1; o < 16; o <<= 1)
                mt = fmaxf(mt, __shfl_xor_sync(0xffffffffu, mt, o));
            float mn = fmaxf(m[i], mt);
            float sc = __expf(m[i] - mn);
            m[i] = mn;
            float rs = 0.f;
#pragma unroll
            for (int j = 0; j < 4; j++) {
                float p = __expf(s[i][j] - mn);
                s[i][j] = p;
                rs += p;
            }
#pragma unroll
            for (int o = 1; o < 16; o <<= 1)
                rs += __shfl_xor_sync(0xffffffffu, rs, o);
            l[i] = l[i] * sc + rs;
#pragma unroll
            for (int j = 0; j < 4; j++) acc[i][j] *= sc;
#pragma unroll
            for (int j = 0; j < 4; j++) Pst[(c0 + j) * QPAD + r0 + i] = s[i][j];
        }
        __syncthreads();

        // O += P V  (8x4 per thread)
        for (int j = 0; j < 64; j++) {
            float4 pa = *(const float4*)(Pst + j * QPAD + r0);
            float4 pb = *(const float4*)(Pst + j * QPAD + r0 + 4);
            float4 vv = *(const float4*)(Vs + j * KPAD + c0);
            float pv[8] = {pa.x, pa.y, pa.z, pa.w, pb.x, pb.y, pb.z, pb.w};
            float vr[4] = {vv.x, vv.y, vv.z, vv.w};
#pragma unroll
            for (int i = 0; i < 8; i++)
#pragma unroll
                for (int jj = 0; jj < 4; jj++) acc[i][jj] += pv[i] * vr[jj];
        }
    }

    // epilogue: normalize, gate, write O + (m, l)
#pragma unroll
    for (int i = 0; i < 8; i++) {
        float f = (1.f / l[i]) * g_gate[b * Nseq + qg0 + r0 + i];
        *(float4*)(g_AT + base + (size_t)(qg0 + r0 + i) * Dmod + c0) =
            make_float4(acc[i][0] * f, acc[i][1] * f, acc[i][2] * f, acc[i][3] * f);
        if (tx == 0) {
            g_m[bh * Nseq + qg0 + r0 + i] = m[i];
            g_l[bh * Nseq + qg0 + r0 + i] = l[i];
        }
    }
}

// ---------------------------------------------------------------------------
// exact entropy: -(sum_j p_j * log(p_j + 1e-6)), one warp per (b,h,q) row
// ---------------------------------------------------------------------------
__global__ void __launch_bounds__(256)
entropy_kernel(float* __restrict__ ent)
{
    const int gid = blockIdx.x * 8 + (threadIdx.x >> 5);
    const int lane = threadIdx.x & 31;
    const int q = gid % Nseq;
    const float mm = g_m[gid];
    const float il = 1.f / g_l[gid];
    const float* Srow = g_S + (size_t)gid * Nseq;
    float a = 0.f;
    for (int j = lane; j <= q; j += 32) {
        float p = __expf(Srow[j] - mm) * il;
        a += p * __logf(p + 1e-6f);
    }
#pragma unroll
    for (int o = 16; o > 0; o >>= 1)
        a += __shfl_xor_sync(0xffffffffu, a, o);
    if (lane == 0) ent[gid] = -a;
}

// ---------------------------------------------------------------------------
extern "C" void kernel_launch(void* const* d_in, const int* in_sizes, int n_in,
                              void* d_out, int out_size)
{
    const float* x   = (const float*)d_in[0];
    // d_in[1] = attn_bias (causal prior handled analytically by loop bounds)
    const float* Wq  = (const float*)d_in[2];
    const float* bq  = (const float*)d_in[3];
    const float* Wk  = (const float*)d_in[4];
    const float* bk  = (const float*)d_in[5];
    const float* Wv  = (const float*)d_in[6];
    const float* bv  = (const float*)d_in[7];
    const float* Wg1 = (const float*)d_in[8];
    const float* bg1 = (const float*)d_in[9];
    const float* Wg2 = (const float*)d_in[10];
    const float* bg2 = (const float*)d_in[11];
    const float* Wo  = (const float*)d_in[12];
    const float* bo  = (const float*)d_in[13];

    float* out = (float*)d_out;

    float *Qp, *Kp, *Vp, *H1p, *ATp, *gp;
    cudaGetSymbolAddress((void**)&Qp,  g_Q);
    cudaGetSymbolAddress((void**)&Kp,  g_K);
    cudaGetSymbolAddress((void**)&Vp,  g_V);
    cudaGetSymbolAddress((void**)&H1p, g_H1);
    cudaGetSymbolAddress((void**)&ATp, g_AT);
    cudaGetSymbolAddress((void**)&gp,  g_gate);

    // fused Q/K/V/G1 projections: N = 4096 across 4 weight segments
    gemm128<<<dim3(32, 24), 256>>>(x, Wq, Wk, Wv, Wg1,
                                   bq, bk, bv, bg1,
                                   Qp, Kp, Vp, H1p, 3);

    gate_kernel<<<ROWS, 256>>>(H1p, Wg2, bg2, gp);

    cudaFuncSetAttribute(flash_kernel,
                         cudaFuncAttributeMaxDynamicSharedMemorySize, FLASH_SMEM);
    flash_kernel<<<dim3(Nseq / 128, BH), 256, FLASH_SMEM>>>();

    entropy_kernel<<<(BH * Nseq) / 8, 256>>>(out + OUT_ELEMS);

    // output projection
    gemm128<<<dim3(8, 24), 256>>>(ATp, Wo, Wo, Wo, Wo,
                                  bo, bo, bo, bo,
                                  out, out, out, out, -1);
}

// round 6
// speedup vs baseline: 6.1052x; 1.2770x over previous
#include <cuda_runtime.h>
#include <cuda_bf16.h>
#include <math.h>
#include <stdint.h>

#define Bdim 2
#define Nseq 1536
#define Dmod 1024
#define Hn   16
#define DHd  64
#define SCALE 0.125f
#define ROWS (Bdim * Nseq)               // 3072
#define OUT_ELEMS ((size_t)ROWS * Dmod)  // 3145728
#define BH (Bdim * Hn)                   // 32

// ---------------------------------------------------------------------------
// scratch (no cudaMalloc allowed)
// ---------------------------------------------------------------------------
__device__ float g_Q [ROWS * Dmod];
__device__ float g_K [ROWS * Dmod];
__device__ float g_V [ROWS * Dmod];
__device__ float g_H1[ROWS * Dmod];
__device__ float g_AT[ROWS * Dmod];
__device__ float g_gate[ROWS];
__device__ float g_m[BH * Nseq];
__device__ float g_l[BH * Nseq];
__device__ float g_S[(size_t)BH * Nseq * Nseq];   // raw scores, 302 MB

// bf16 split operands
__device__ __nv_bfloat16 g_xhi[ROWS * Dmod];
__device__ __nv_bfloat16 g_xlo[ROWS * Dmod];
__device__ __nv_bfloat16 g_ahi[ROWS * Dmod];
__device__ __nv_bfloat16 g_alo[ROWS * Dmod];
__device__ __nv_bfloat16 g_Wh[5 * Dmod * Dmod];   // transposed K-major, hi
__device__ __nv_bfloat16 g_Wl[5 * Dmod * Dmod];   // transposed K-major, lo

// ---------------------------------------------------------------------------
// baseline-ISA helpers: ldmatrix / mma.sync / cp.async (no 'a'-only features)
// ---------------------------------------------------------------------------
__device__ __forceinline__ uint32_t smem_u32(const void* p) {
    uint32_t a;
    asm("{ .reg .u64 t; cvta.to.shared.u64 t, %1; cvt.u32.u64 %0, t; }"
        : "=r"(a) : "l"(p));
    return a;
}

#define LDSM4(r0, r1, r2, r3, a)                                              \
    asm volatile("ldmatrix.sync.aligned.m8n8.x4.shared.b16 {%0,%1,%2,%3}, [%4];" \
                 : "=r"(r0), "=r"(r1), "=r"(r2), "=r"(r3) : "r"(a))

#define MMA16816(d, a, b)                                                     \
    asm volatile("mma.sync.aligned.m16n8k16.row.col.f32.bf16.bf16.f32 "       \
                 "{%0,%1,%2,%3}, {%4,%5,%6,%7}, {%8,%9}, {%0,%1,%2,%3};"      \
                 : "+f"((d)[0]), "+f"((d)[1]), "+f"((d)[2]), "+f"((d)[3])     \
                 : "r"((a)[0]), "r"((a)[1]), "r"((a)[2]), "r"((a)[3]),        \
                   "r"((b)[0]), "r"((b)[1]))

#define CP_ASYNC16(dst, src)                                                  \
    asm volatile("cp.async.cg.shared.global [%0], [%1], 16;"                  \
                 :: "r"(dst), "l"(src))
#define CP_COMMIT() asm volatile("cp.async.commit_group;" ::: "memory")
#define CP_WAIT1()  asm volatile("cp.async.wait_group 1;" ::: "memory")
#define CP_WAIT0()  asm volatile("cp.async.wait_group 0;" ::: "memory")

// ---------------------------------------------------------------------------
// split fp32 -> bf16 hi/lo (vectorized x4)
// ---------------------------------------------------------------------------
__global__ void __launch_bounds__(256)
xsplit(const float* __restrict__ A, __nv_bfloat16* __restrict__ H,
       __nv_bfloat16* __restrict__ L)
{
    int i = blockIdx.x * 256 + threadIdx.x;
    float4 v = ((const float4*)A)[i];
    float f[4] = {v.x, v.y, v.z, v.w};
    __nv_bfloat16 h[4], l[4];
#pragma unroll
    for (int j = 0; j < 4; j++) {
        h[j] = __float2bfloat16(f[j]);
        l[j] = __float2bfloat16(f[j] - __bfloat162float(h[j]));
    }
    ((__nv_bfloat162*)H)[2 * i]     = __nv_bfloat162(h[0], h[1]);
    ((__nv_bfloat162*)H)[2 * i + 1] = __nv_bfloat162(h[2], h[3]);
    ((__nv_bfloat162*)L)[2 * i]     = __nv_bfloat162(l[0], l[1]);
    ((__nv_bfloat162*)L)[2 * i + 1] = __nv_bfloat162(l[2], l[3]);
}

// ---------------------------------------------------------------------------
// transpose + split: WT[n][k] = W[k][n] -> bf16 hi/lo
// ---------------------------------------------------------------------------
__global__ void __launch_bounds__(256)
wsplit(const float* __restrict__ W, __nv_bfloat16* __restrict__ Th,
       __nv_bfloat16* __restrict__ Tl)
{
    __shared__ float t[32][33];
    const int n0 = blockIdx.x << 5, k0 = blockIdx.y << 5;
    const int tx = threadIdx.x & 31, ty = threadIdx.x >> 5;  // 32x8
#pragma unroll
    for (int j = 0; j < 32; j += 8)
        t[ty + j][tx] = W[(size_t)(k0 + ty + j) * Dmod + n0 + tx];
    __syncthreads();
#pragma unroll
    for (int j = 0; j < 32; j += 8) {
        float v = t[tx][ty + j];
        __nv_bfloat16 h = __float2bfloat16(v);
        size_t o = (size_t)(n0 + ty + j) * Dmod + k0 + tx;
        Th[o] = h;
        Tl[o] = __float2bfloat16(v - __bfloat162float(h));
    }
}

// ---------------------------------------------------------------------------
// mma.sync split-bf16 GEMM: C[3072x1024] = A @ W + bias (3 hi/lo passes)
// 128x128 tile per CTA, 8 warps (2m x 4n), warp tile 64x32, k-chunk 32,
// cp.async double-buffered. grid = (8, 24, nseg).
// ---------------------------------------------------------------------------
#define SPAD 40        // smem row stride in bf16 (80 B, ldmatrix conflict-free)
#define NCH  96        // 3 passes x 32 k-chunks

__global__ void __launch_bounds__(256)
mma_gemm(const __nv_bfloat16* __restrict__ Ahi, const __nv_bfloat16* __restrict__ Alo,
         const __nv_bfloat16* __restrict__ W0h, const __nv_bfloat16* __restrict__ W0l,
         const __nv_bfloat16* __restrict__ W1h, const __nv_bfloat16* __restrict__ W1l,
         const __nv_bfloat16* __restrict__ W2h, const __nv_bfloat16* __restrict__ W2l,
         const __nv_bfloat16* __restrict__ W3h, const __nv_bfloat16* __restrict__ W3l,
         const float* __restrict__ b0, const float* __restrict__ b1,
         const float* __restrict__ b2, const float* __restrict__ b3,
         float* __restrict__ C0, float* __restrict__ C1,
         float* __restrict__ C2, float* __restrict__ C3, int actseg)
{
    __shared__ __nv_bfloat16 As[2][128 * SPAD];
    __shared__ __nv_bfloat16 Bs[2][128 * SPAD];

    const int tid = threadIdx.x, wid = tid >> 5, lane = tid & 31;
    const int n0 = blockIdx.x << 7, m0 = blockIdx.y << 7;
    const int seg = blockIdx.z;
    const __nv_bfloat16* Wh = seg == 0 ? W0h : seg == 1 ? W1h : seg == 2 ? W2h : W3h;
    const __nv_bfloat16* Wl = seg == 0 ? W0l : seg == 1 ? W1l : seg == 2 ? W2l : W3l;
    const float* Bp = seg == 0 ? b0 : seg == 1 ? b1 : seg == 2 ? b2 : b3;
    float* C = seg == 0 ? C0 : seg == 1 ? C1 : seg == 2 ? C2 : C3;
    const bool act = (seg == actseg);

    const int wm = (wid & 1) << 6;        // warp m offset: 0 / 64
    const int wn = (wid >> 1) << 5;       // warp n offset: 0 / 32 / 64 / 96

    float acc[4][4][4];
#pragma unroll
    for (int i = 0; i < 4; i++)
#pragma unroll
        for (int j = 0; j < 4; j++)
#pragma unroll
            for (int c = 0; c < 4; c++) acc[i][j][c] = 0.f;

    // per-thread cp.async slots: 4 A-chunks + 4 B-chunks per stage
    const int lrow = tid >> 1;            // 0..127
    const int lch  = (tid & 1) << 1;      // 0 or 2 (two 16B chunks each)

    auto load = [&](int s) {
        const int st = s & 1;
        const int p = s >> 5, k0 = (s & 31) << 5;
        const __nv_bfloat16* Ag = ((p < 2) ? Ahi : Alo) + (size_t)(m0 + lrow) * Dmod + k0;
        const __nv_bfloat16* Bg = ((p == 1) ? Wl : Wh)  + (size_t)(n0 + lrow) * Dmod + k0;
        uint32_t sa = smem_u32(&As[st][lrow * SPAD]);
        uint32_t sb = smem_u32(&Bs[st][lrow * SPAD]);
#pragma unroll
        for (int c = 0; c < 2; c++) {
            CP_ASYNC16(sa + (lch + c) * 16, Ag + (lch + c) * 8);
            CP_ASYNC16(sb + (lch + c) * 16, Bg + (lch + c) * 8);
        }
    };

    // ldmatrix lane addresses (byte offsets within a stage)
    const uint32_t a_off = (uint32_t)((wm + (lane & 15)) * SPAD + (lane >> 4) * 8) * 2;
    const uint32_t b_off = (uint32_t)((wn + ((lane >> 3) & 1) * 8 + (lane & 7)) * SPAD
                                      + (lane >> 4) * 8) * 2;

    load(0); CP_COMMIT();

    for (int s = 0; s < NCH; s++) {
        if (s + 1 < NCH) { load(s + 1); CP_COMMIT(); CP_WAIT1(); }
        else CP_WAIT0();
        __syncthreads();

        const uint32_t ab = smem_u32(As[s & 1]) + a_off;
        const uint32_t bb = smem_u32(Bs[s & 1]) + b_off;

#pragma unroll
        for (int kh = 0; kh < 2; kh++) {
            uint32_t af[4][4], bf[4][2];
#pragma unroll
            for (int mi = 0; mi < 4; mi++)
                LDSM4(af[mi][0], af[mi][1], af[mi][2], af[mi][3],
                      ab + mi * 16 * SPAD * 2 + kh * 32);
#pragma unroll
            for (int nq = 0; nq < 2; nq++)
                LDSM4(bf[2 * nq][0], bf[2 * nq + 1][0],
                      bf[2 * nq][1], bf[2 * nq + 1][1],
                      bb + nq * 16 * SPAD * 2 + kh * 32);
#pragma unroll
            for (int mi = 0; mi < 4; mi++)
#pragma unroll
                for (int nj = 0; nj < 4; nj++)
                    MMA16816(acc[mi][nj], af[mi], bf[nj]);
        }
        __syncthreads();
    }

    // epilogue: bias + optional exact GELU, write fp32
    const int gp = lane >> 2, t4 = lane & 3;
#pragma unroll
    for (int mi = 0; mi < 4; mi++) {
#pragma unroll
        for (int nj = 0; nj < 4; nj++) {
            const int col = n0 + wn + nj * 8 + t4 * 2;
            const float bi0 = Bp[col], bi1 = Bp[col + 1];
#pragma unroll
            for (int h = 0; h < 2; h++) {
                const int row = m0 + wm + mi * 16 + gp + h * 8;
                float v0 = acc[mi][nj][2 * h + 0] + bi0;
                float v1 = acc[mi][nj][2 * h + 1] + bi1;
                if (act) {
                    v0 = 0.5f * v0 * (1.0f + erff(v0 * 0.70710678118654752f));
                    v1 = 0.5f * v1 * (1.0f + erff(v1 * 0.70710678118654752f));
                }
                *(float2*)(C + (size_t)row * Dmod + col) = make_float2(v0, v1);
            }
        }
    }
}

// ---------------------------------------------------------------------------
// gate[row] = sigmoid(dot(H1[row,:], Wg2) + bg2)
// ---------------------------------------------------------------------------
__global__ void __launch_bounds__(256)
gate_kernel(const float* __restrict__ H1,
            const float* __restrict__ Wg2,
            const float* __restrict__ bg2,
            float* __restrict__ gate)
{
    __shared__ float red[8];
    const int row = blockIdx.x;
    const float* hp = H1 + (size_t)row * Dmod;
    float loc = 0.f;
    for (int k = threadIdx.x; k < Dmod; k += blockDim.x)
        loc += hp[k] * Wg2[k];
#pragma unroll
    for (int o = 16; o > 0; o >>= 1)
        loc += __shfl_xor_sync(0xffffffffu, loc, o);
    if ((threadIdx.x & 31) == 0) red[threadIdx.x >> 5] = loc;
    __syncthreads();
    if (threadIdx.x == 0) {
        float s = 0.f;
        for (int i = 0; i < 8; i++) s += red[i];
        gate[row] = 1.f / (1.f + __expf(-(s + bg2[0])));
    }
}

// ---------------------------------------------------------------------------
// Flash attention (fp32): one CTA per (b, h, 128-query tile). 256 threads.
// ---------------------------------------------------------------------------
#define QPAD 132
#define KPAD 68
#define FLASH_SMEM ((64 * QPAD + 64 * KPAD + 64 * KPAD + 64 * QPAD) * 4)

__global__ void __launch_bounds__(256)
flash_kernel()
{
    extern __shared__ float smf[];
    float* Qst = smf;
    float* Kst = Qst + 64 * QPAD;
    float* Vs  = Kst + 64 * KPAD;
    float* Pst = Vs  + 64 * KPAD;

    const int qt = blockIdx.x;
    const int bh = blockIdx.y;
    const int b = bh >> 4, h = bh & 15;
    const int qg0 = qt << 7;
    const int tid = threadIdx.x;
    const int tx = tid & 15, ty = tid >> 4;
    const int r0 = ty << 3, c0 = tx << 2;
    const size_t base = (size_t)b * Nseq * Dmod + (size_t)h * DHd;

    for (int i = tid; i < 128 * 16; i += 256) {
        int r = i >> 4, c = (i & 15) << 2;
        float4 v = *(const float4*)(g_Q + base + (size_t)(qg0 + r) * Dmod + c);
        Qst[(c + 0) * QPAD + r] = v.x * SCALE;
        Qst[(c + 1) * QPAD + r] = v.y * SCALE;
        Qst[(c + 2) * QPAD + r] = v.z * SCALE;
        Qst[(c + 3) * QPAD + r] = v.w * SCALE;
    }

    float m[8], l[8], acc[8][4];
#pragma unroll
    for (int i = 0; i < 8; i++) {
        m[i] = -1e30f; l[i] = 0.f;
#pragma unroll
        for (int j = 0; j < 4; j++) acc[i][j] = 0.f;
    }

    const size_t sbase = (size_t)bh * Nseq * Nseq;
    const int ktiles = 2 * qt + 2;

    for (int kt = 0; kt < ktiles; kt++) {
        const int k0 = kt << 6;
        __syncthreads();
        for (int i = tid; i < 64 * 16; i += 256) {
            int r = i >> 4, c = (i & 15) << 2;
            float4 kv = *(const float4*)(g_K + base + (size_t)(k0 + r) * Dmod + c);
            Kst[(c + 0) * KPAD + r] = kv.x;
            Kst[(c + 1) * KPAD + r] = kv.y;
            Kst[(c + 2) * KPAD + r] = kv.z;
            Kst[(c + 3) * KPAD + r] = kv.w;
            *(float4*)(Vs + r * KPAD + c) =
                *(const float4*)(g_V + base + (size_t)(k0 + r) * Dmod + c);
        }
        __syncthreads();

        float s[8][4];
#pragma unroll
        for (int i = 0; i < 8; i++)
#pragma unroll
            for (int j = 0; j < 4; j++) s[i][j] = 0.f;
        for (int d = 0; d < 64; d++) {
            float4 qa = *(const float4*)(Qst + d * QPAD + r0);
            float4 qb = *(const float4*)(Qst + d * QPAD + r0 + 4);
            float4 kk = *(const float4*)(Kst + d * KPAD + c0);
            float qv[8] = {qa.x, qa.y, qa.z, qa.w, qb.x, qb.y, qb.z, qb.w};
            float kv[4] = {kk.x, kk.y, kk.z, kk.w};
#pragma unroll
            for (int i = 0; i < 8; i++)
#pragma unroll
                for (int j = 0; j < 4; j++) s[i][j] += qv[i] * kv[j];
        }

#pragma unroll
        for (int i = 0; i < 8; i++)
            *(float4*)(g_S + sbase + (size_t)(qg0 + r0 + i) * Nseq + k0 + c0) =
                make_float4(s[i][0], s[i][1], s[i][2], s[i][3]);

        if (kt >= 2 * qt) {
#pragma unroll
            for (int i = 0; i < 8; i++)
#pragma unroll
                for (int j = 0; j < 4; j++)
                    if (k0 + c0 + j > qg0 + r0 + i) s[i][j] = -1e30f;
        }

#pragma unroll
        for (int i = 0; i < 8; i++) {
            float mt = fmaxf(fmaxf(s[i][0], s[i][1]), fmaxf(s[i][2], s[i][3]));
#pragma unroll
            for (int o = 1; o < 16; o <<= 1)
                mt = fmaxf(mt, __shfl_xor_sync(0xffffffffu, mt, o));
            float mn = fmaxf(m[i], mt);
            float sc = __expf(m[i] - mn);
            m[i] = mn;
            float rs = 0.f;
#pragma unroll
            for (int j = 0; j < 4; j++) {
                float p = __expf(s[i][j] - mn);
                s[i][j] = p;
                rs += p;
            }
#pragma unroll
            for (int o = 1; o < 16; o <<= 1)
                rs += __shfl_xor_sync(0xffffffffu, rs, o);
            l[i] = l[i] * sc + rs;
#pragma unroll
            for (int j = 0; j < 4; j++) acc[i][j] *= sc;
#pragma unroll
            for (int j = 0; j < 4; j++) Pst[(c0 + j) * QPAD + r0 + i] = s[i][j];
        }
        __syncthreads();

        for (int j = 0; j < 64; j++) {
            float4 pa = *(const float4*)(Pst + j * QPAD + r0);
            float4 pb = *(const float4*)(Pst + j * QPAD + r0 + 4);
            float4 vv = *(const float4*)(Vs + j * KPAD + c0);
            float pv[8] = {pa.x, pa.y, pa.z, pa.w, pb.x, pb.y, pb.z, pb.w};
            float vr[4] = {vv.x, vv.y, vv.z, vv.w};
#pragma unroll
            for (int i = 0; i < 8; i++)
#pragma unroll
                for (int jj = 0; jj < 4; jj++) acc[i][jj] += pv[i] * vr[jj];
        }
    }

#pragma unroll
    for (int i = 0; i < 8; i++) {
        float f = (1.f / l[i]) * g_gate[b * Nseq + qg0 + r0 + i];
        *(float4*)(g_AT + base + (size_t)(qg0 + r0 + i) * Dmod + c0) =
            make_float4(acc[i][0] * f, acc[i][1] * f, acc[i][2] * f, acc[i][3] * f);
        if (tx == 0) {
            g_m[bh * Nseq + qg0 + r0 + i] = m[i];
            g_l[bh * Nseq + qg0 + r0 + i] = l[i];
        }
    }
}

// ---------------------------------------------------------------------------
// exact entropy: -(sum_j p_j * log(p_j + 1e-6)), one warp per (b,h,q) row
// ---------------------------------------------------------------------------
__global__ void __launch_bounds__(256)
entropy_kernel(float* __restrict__ ent)
{
    const int gid = blockIdx.x * 8 + (threadIdx.x >> 5);
    const int lane = threadIdx.x & 31;
    const int q = gid % Nseq;
    const float mm = g_m[gid];
    const float il = 1.f / g_l[gid];
    const float* Srow = g_S + (size_t)gid * Nseq;
    float a = 0.f;
    for (int j = lane; j <= q; j += 32) {
        float p = __expf(Srow[j] - mm) * il;
        a += p * __logf(p + 1e-6f);
    }
#pragma unroll
    for (int o = 16; o > 0; o >>= 1)
        a += __shfl_xor_sync(0xffffffffu, a, o);
    if (lane == 0) ent[gid] = -a;
}

// ---------------------------------------------------------------------------
extern "C" void kernel_launch(void* const* d_in, const int* in_sizes, int n_in,
                              void* d_out, int out_size)
{
    const float* x   = (const float*)d_in[0];
    // d_in[1] = attn_bias (causal prior handled analytically by loop bounds)
    const float* Wq  = (const float*)d_in[2];
    const float* bq  = (const float*)d_in[3];
    const float* Wk  = (const float*)d_in[4];
    const float* bk  = (const float*)d_in[5];
    const float* Wv  = (const float*)d_in[6];
    const float* bv  = (const float*)d_in[7];
    const float* Wg1 = (const float*)d_in[8];
    const float* bg1 = (const float*)d_in[9];
    const float* Wg2 = (const float*)d_in[10];
    const float* bg2 = (const float*)d_in[11];
    const float* Wo  = (const float*)d_in[12];
    const float* bo  = (const float*)d_in[13];

    float* out = (float*)d_out;

    float *Qp, *Kp, *Vp, *H1p, *ATp, *gp;
    __nv_bfloat16 *xh, *xl, *ah, *al, *Whp, *Wlp;
    cudaGetSymbolAddress((void**)&Qp,  g_Q);
    cudaGetSymbolAddress((void**)&Kp,  g_K);
    cudaGetSymbolAddress((void**)&Vp,  g_V);
    cudaGetSymbolAddress((void**)&H1p, g_H1);
    cudaGetSymbolAddress((void**)&ATp, g_AT);
    cudaGetSymbolAddress((void**)&gp,  g_gate);
    cudaGetSymbolAddress((void**)&xh,  g_xhi);
    cudaGetSymbolAddress((void**)&xl,  g_xlo);
    cudaGetSymbolAddress((void**)&ah,  g_ahi);
    cudaGetSymbolAddress((void**)&al,  g_alo);
    cudaGetSymbolAddress((void**)&Whp, g_Wh);
    cudaGetSymbolAddress((void**)&Wlp, g_Wl);

    const size_t WSZ = (size_t)Dmod * Dmod;

    cudaFuncSetAttribute(flash_kernel, cudaFuncAttributeMaxDynamicSharedMemorySize, FLASH_SMEM);

    // weight transpose + split (K-major bf16 hi/lo): slots 0..4 = Wq,Wk,Wv,Wg1,Wo
    dim3 wtg(32, 32);
    wsplit<<<wtg, 256>>>(Wq,  Whp + 0 * WSZ, Wlp + 0 * WSZ);
    wsplit<<<wtg, 256>>>(Wk,  Whp + 1 * WSZ, Wlp + 1 * WSZ);
    wsplit<<<wtg, 256>>>(Wv,  Whp + 2 * WSZ, Wlp + 2 * WSZ);
    wsplit<<<wtg, 256>>>(Wg1, Whp + 3 * WSZ, Wlp + 3 * WSZ);
    wsplit<<<wtg, 256>>>(Wo,  Whp + 4 * WSZ, Wlp + 4 * WSZ);

    // split x
    xsplit<<<OUT_ELEMS / 1024, 256>>>(x, xh, xl);

    // fused Q/K/V/G1 projections on tensor pipe (GELU on seg 3)
    mma_gemm<<<dim3(8, 24, 4), 256>>>(
        xh, xl,
        Whp + 0 * WSZ, Wlp + 0 * WSZ, Whp + 1 * WSZ, Wlp + 1 * WSZ,
        Whp + 2 * WSZ, Wlp + 2 * WSZ, Whp + 3 * WSZ, Wlp + 3 * WSZ,
        bq, bk, bv, bg1,
        Qp, Kp, Vp, H1p, 3);

    gate_kernel<<<ROWS, 256>>>(H1p, Wg2, bg2, gp);

    flash_kernel<<<dim3(Nseq / 128, BH), 256, FLASH_SMEM>>>();

    entropy_kernel<<<(BH * Nseq) / 8, 256>>>(out + OUT_ELEMS);

    // output projection on tensor pipe
    xsplit<<<OUT_ELEMS / 1024, 256>>>(ATp, ah, al);
    mma_gemm<<<dim3(8, 24, 1), 256>>>(
        ah, al,
        Whp + 4 * WSZ, Wlp + 4 * WSZ, Whp + 4 * WSZ, Wlp + 4 * WSZ,
        Whp + 4 * WSZ, Wlp + 4 * WSZ, Whp + 4 * WSZ, Wlp + 4 * WSZ,
        bo, bo, bo, bo,
        out, out, out, out, -1);
}

// round 9
// speedup vs baseline: 8.4746x; 1.3881x over previous
#include <cuda_runtime.h>
#include <cuda_bf16.h>
#include <math.h>
#include <stdint.h>

#define Bdim 2
#define Nseq 1536
#define Dmod 1024
#define Hn   16
#define DHd  64
#define SCALE 0.125f
#define ROWS (Bdim * Nseq)               // 3072
#define OUT_ELEMS ((size_t)ROWS * Dmod)  // 3145728
#define BH (Bdim * Hn)                   // 32

// ---------------------------------------------------------------------------
// scratch (no cudaMalloc allowed)
// ---------------------------------------------------------------------------
__device__ float g_Q [ROWS * Dmod];
__device__ float g_K [ROWS * Dmod];
__device__ float g_V [ROWS * Dmod];
__device__ float g_H1[ROWS * Dmod];
__device__ float g_AT[ROWS * Dmod];
__device__ float g_gate[ROWS];

// bf16 split operands
__device__ __nv_bfloat16 g_xhi[ROWS * Dmod];
__device__ __nv_bfloat16 g_xlo[ROWS * Dmod];
__device__ __nv_bfloat16 g_ahi[ROWS * Dmod];
__device__ __nv_bfloat16 g_alo[ROWS * Dmod];
__device__ __nv_bfloat16 g_Wh[5 * Dmod * Dmod];   // transposed K-major, hi
__device__ __nv_bfloat16 g_Wl[5 * Dmod * Dmod];   // transposed K-major, lo
// flash operands (bf16 hi/lo of Q*SCALE, K, V)
__device__ __nv_bfloat16 g_qh[ROWS * Dmod];
__device__ __nv_bfloat16 g_ql[ROWS * Dmod];
__device__ __nv_bfloat16 g_kh[ROWS * Dmod];
__device__ __nv_bfloat16 g_kl[ROWS * Dmod];
__device__ __nv_bfloat16 g_vh[ROWS * Dmod];
__device__ __nv_bfloat16 g_vl[ROWS * Dmod];

// ---------------------------------------------------------------------------
// baseline-ISA helpers
// ---------------------------------------------------------------------------
__device__ __forceinline__ uint32_t smem_u32(const void* p) {
    uint32_t a;
    asm("{ .reg .u64 t; cvta.to.shared.u64 t, %1; cvt.u32.u64 %0, t; }"
        : "=r"(a) : "l"(p));
    return a;
}

#define LDSM4(r0, r1, r2, r3, a)                                              \
    asm volatile("ldmatrix.sync.aligned.m8n8.x4.shared.b16 {%0,%1,%2,%3}, [%4];" \
                 : "=r"(r0), "=r"(r1), "=r"(r2), "=r"(r3) : "r"(a))
#define LDSM4T(r0, r1, r2, r3, a)                                             \
    asm volatile("ldmatrix.sync.aligned.m8n8.x4.trans.shared.b16 {%0,%1,%2,%3}, [%4];" \
                 : "=r"(r0), "=r"(r1), "=r"(r2), "=r"(r3) : "r"(a))

#define MMA16816(d, a, b)                                                     \
    asm volatile("mma.sync.aligned.m16n8k16.row.col.f32.bf16.bf16.f32 "       \
                 "{%0,%1,%2,%3}, {%4,%5,%6,%7}, {%8,%9}, {%0,%1,%2,%3};"      \
                 : "+f"((d)[0]), "+f"((d)[1]), "+f"((d)[2]), "+f"((d)[3])     \
                 : "r"((a)[0]), "r"((a)[1]), "r"((a)[2]), "r"((a)[3]),        \
                   "r"((b)[0]), "r"((b)[1]))

#define MMAS(d, a0_, a1_, a2_, a3_, b0_, b1_)                                 \
    asm volatile("mma.sync.aligned.m16n8k16.row.col.f32.bf16.bf16.f32 "       \
                 "{%0,%1,%2,%3}, {%4,%5,%6,%7}, {%8,%9}, {%0,%1,%2,%3};"      \
                 : "+f"((d)[0]), "+f"((d)[1]), "+f"((d)[2]), "+f"((d)[3])     \
                 : "r"(a0_), "r"(a1_), "r"(a2_), "r"(a3_), "r"(b0_), "r"(b1_))

#define CP_ASYNC16(dst, src)                                                  \
    asm volatile("cp.async.cg.shared.global [%0], [%1], 16;"                  \
                 :: "r"(dst), "l"(src))
#define CP_COMMIT() asm volatile("cp.async.commit_group;" ::: "memory")
#define CP_WAIT1()  asm volatile("cp.async.wait_group 1;" ::: "memory")
#define CP_WAIT0()  asm volatile("cp.async.wait_group 0;" ::: "memory")

// pack two f32 -> bf16x2 register (arg order: lo first)
__device__ __forceinline__ uint32_t pack_bf2(float lo, float hi) {
    uint32_t r;
    asm("cvt.rn.bf16x2.f32 %0, %1, %2;" : "=r"(r) : "f"(hi), "f"(lo));
    return r;
}

// ---------------------------------------------------------------------------
// split fp32 -> bf16 hi/lo with scale (vectorized x4)
// ---------------------------------------------------------------------------
__global__ void __launch_bounds__(256)
ssplit(const float* __restrict__ A, __nv_bfloat16* __restrict__ H,
       __nv_bfloat16* __restrict__ L, float sc)
{
    int i = blockIdx.x * 256 + threadIdx.x;
    float4 v = ((const float4*)A)[i];
    float f[4] = {v.x * sc, v.y * sc, v.z * sc, v.w * sc};
    __nv_bfloat16 h[4], l[4];
#pragma unroll
    for (int j = 0; j < 4; j++) {
        h[j] = __float2bfloat16(f[j]);
        l[j] = __float2bfloat16(f[j] - __bfloat162float(h[j]));
    }
    ((__nv_bfloat162*)H)[2 * i]     = __nv_bfloat162(h[0], h[1]);
    ((__nv_bfloat162*)H)[2 * i + 1] = __nv_bfloat162(h[2], h[3]);
    ((__nv_bfloat162*)L)[2 * i]     = __nv_bfloat162(l[0], l[1]);
    ((__nv_bfloat162*)L)[2 * i + 1] = __nv_bfloat162(l[2], l[3]);
}

// ---------------------------------------------------------------------------
// transpose + split: WT[n][k] = W[k][n] -> bf16 hi/lo
// ---------------------------------------------------------------------------
__global__ void __launch_bounds__(256)
wsplit(const float* __restrict__ W, __nv_bfloat16* __restrict__ Th,
       __nv_bfloat16* __restrict__ Tl)
{
    __shared__ float t[32][33];
    const int n0 = blockIdx.x << 5, k0 = blockIdx.y << 5;
    const int tx = threadIdx.x & 31, ty = threadIdx.x >> 5;  // 32x8
#pragma unroll
    for (int j = 0; j < 32; j += 8)
        t[ty + j][tx] = W[(size_t)(k0 + ty + j) * Dmod + n0 + tx];
    __syncthreads();
#pragma unroll
    for (int j = 0; j < 32; j += 8) {
        float v = t[tx][ty + j];
        __nv_bfloat16 h = __float2bfloat16(v);
        size_t o = (size_t)(n0 + ty + j) * Dmod + k0 + tx;
        Th[o] = h;
        Tl[o] = __float2bfloat16(v - __bfloat162float(h));
    }
}

// ---------------------------------------------------------------------------
// mma.sync split-bf16 GEMM (proven in R6): C = A @ W + bias, 128x128 tiles
// ---------------------------------------------------------------------------
#define SPAD 40
#define NCH  96

__global__ void __launch_bounds__(256)
mma_gemm(const __nv_bfloat16* __restrict__ Ahi, const __nv_bfloat16* __restrict__ Alo,
         const __nv_bfloat16* __restrict__ W0h, const __nv_bfloat16* __restrict__ W0l,
         const __nv_bfloat16* __restrict__ W1h, const __nv_bfloat16* __restrict__ W1l,
         const __nv_bfloat16* __restrict__ W2h, const __nv_bfloat16* __restrict__ W2l,
         const __nv_bfloat16* __restrict__ W3h, const __nv_bfloat16* __restrict__ W3l,
         const float* __restrict__ b0, const float* __restrict__ b1,
         const float* __restrict__ b2, const float* __restrict__ b3,
         float* __restrict__ C0, float* __restrict__ C1,
         float* __restrict__ C2, float* __restrict__ C3, int actseg)
{
    __shared__ __nv_bfloat16 As[2][128 * SPAD];
    __shared__ __nv_bfloat16 Bs[2][128 * SPAD];

    const int tid = threadIdx.x, wid = tid >> 5, lane = tid & 31;
    const int n0 = blockIdx.x << 7, m0 = blockIdx.y << 7;
    const int seg = blockIdx.z;
    const __nv_bfloat16* Wh = seg == 0 ? W0h : seg == 1 ? W1h : seg == 2 ? W2h : W3h;
    const __nv_bfloat16* Wl = seg == 0 ? W0l : seg == 1 ? W1l : seg == 2 ? W2l : W3l;
    const float* Bp = seg == 0 ? b0 : seg == 1 ? b1 : seg == 2 ? b2 : b3;
    float* C = seg == 0 ? C0 : seg == 1 ? C1 : seg == 2 ? C2 : C3;
    const bool act = (seg == actseg);

    const int wm = (wid & 1) << 6;
    const int wn = (wid >> 1) << 5;

    float acc[4][4][4];
#pragma unroll
    for (int i = 0; i < 4; i++)
#pragma unroll
        for (int j = 0; j < 4; j++)
#pragma unroll
            for (int c = 0; c < 4; c++) acc[i][j][c] = 0.f;

    const int lrow = tid >> 1;
    const int lch  = (tid & 1) << 1;

    auto load = [&](int s) {
        const int st = s & 1;
        const int p = s >> 5, k0 = (s & 31) << 5;
        const __nv_bfloat16* Ag = ((p < 2) ? Ahi : Alo) + (size_t)(m0 + lrow) * Dmod + k0;
        const __nv_bfloat16* Bg = ((p == 1) ? Wl : Wh)  + (size_t)(n0 + lrow) * Dmod + k0;
        uint32_t sa = smem_u32(&As[st][lrow * SPAD]);
        uint32_t sb = smem_u32(&Bs[st][lrow * SPAD]);
#pragma unroll
        for (int c = 0; c < 2; c++) {
            CP_ASYNC16(sa + (lch + c) * 16, Ag + (lch + c) * 8);
            CP_ASYNC16(sb + (lch + c) * 16, Bg + (lch + c) * 8);
        }
    };

    const uint32_t a_off = (uint32_t)((wm + (lane & 15)) * SPAD + (lane >> 4) * 8) * 2;
    const uint32_t b_off = (uint32_t)((wn + ((lane >> 3) & 1) * 8 + (lane & 7)) * SPAD
                                      + (lane >> 4) * 8) * 2;

    load(0); CP_COMMIT();

    for (int s = 0; s < NCH; s++) {
        if (s + 1 < NCH) { load(s + 1); CP_COMMIT(); CP_WAIT1(); }
        else CP_WAIT0();
        __syncthreads();

        const uint32_t ab = smem_u32(As[s & 1]) + a_off;
        const uint32_t bb = smem_u32(Bs[s & 1]) + b_off;

#pragma unroll
        for (int kh = 0; kh < 2; kh++) {
            uint32_t af[4][4], bf[4][2];
#pragma unroll
            for (int mi = 0; mi < 4; mi++)
                LDSM4(af[mi][0], af[mi][1], af[mi][2], af[mi][3],
                      ab + mi * 16 * SPAD * 2 + kh * 32);
#pragma unroll
            for (int nq = 0; nq < 2; nq++)
                LDSM4(bf[2 * nq][0], bf[2 * nq + 1][0],
                      bf[2 * nq][1], bf[2 * nq + 1][1],
                      bb + nq * 16 * SPAD * 2 + kh * 32);
#pragma unroll
            for (int mi = 0; mi < 4; mi++)
#pragma unroll
                for (int nj = 0; nj < 4; nj++)
                    MMA16816(acc[mi][nj], af[mi], bf[nj]);
        }
        __syncthreads();
    }

    const int gp = lane >> 2, t4 = lane & 3;
#pragma unroll
    for (int mi = 0; mi < 4; mi++) {
#pragma unroll
        for (int nj = 0; nj < 4; nj++) {
            const int col = n0 + wn + nj * 8 + t4 * 2;
            const float bi0 = Bp[col], bi1 = Bp[col + 1];
#pragma unroll
            for (int h = 0; h < 2; h++) {
                const int row = m0 + wm + mi * 16 + gp + h * 8;
                float v0 = acc[mi][nj][2 * h + 0] + bi0;
                float v1 = acc[mi][nj][2 * h + 1] + bi1;
                if (act) {
                    v0 = 0.5f * v0 * (1.0f + erff(v0 * 0.70710678118654752f));
                    v1 = 0.5f * v1 * (1.0f + erff(v1 * 0.70710678118654752f));
                }
                *(float2*)(C + (size_t)row * Dmod + col) = make_float2(v0, v1);
            }
        }
    }
}

// ---------------------------------------------------------------------------
// gate[row] = sigmoid(dot(H1[row,:], Wg2) + bg2)
// ---------------------------------------------------------------------------
__global__ void __launch_bounds__(256)
gate_kernel(const float* __restrict__ H1,
            const float* __restrict__ Wg2,
            const float* __restrict__ bg2,
            float* __restrict__ gate)
{
    __shared__ float red[8];
    const int row = blockIdx.x;
    const float* hp = H1 + (size_t)row * Dmod;
    float loc = 0.f;
    for (int k = threadIdx.x; k < Dmod; k += blockDim.x)
        loc += hp[k] * Wg2[k];
#pragma unroll
    for (int o = 16; o > 0; o >>= 1)
        loc += __shfl_xor_sync(0xffffffffu, loc, o);
    if ((threadIdx.x & 31) == 0) red[threadIdx.x >> 5] = loc;
    __syncthreads();
    if (threadIdx.x == 0) {
        float s = 0.f;
        for (int i = 0; i < 8; i++) s += red[i];
        gate[row] = 1.f / (1.f + __expf(-(s + bg2[0])));
    }
}

// ---------------------------------------------------------------------------
// mma.sync flash attention, online softmax + online entropy.
// CTA = (128-query tile, bh). 8 warps x 16 q-rows each. 64-key tiles.
// QK: Qh*Kh + Ql*Kh + Qh*Kl;  PV: Ph*Vh + Pl*Vh + Ph*Vl.
// entropy = log l - E/l - (q+1)*1e-6,  E = sum e^(s-m)*(s-m), online-rescaled.
// SPF = 72 bf16 = 144 B row stride: multiple of 16 (cp.async/ldmatrix legal),
// 36-word stride -> rows 0..7 hit disjoint 4-bank groups (conflict-free).
// ---------------------------------------------------------------------------
#define SPF 72
#define QSZ (128 * SPF)
#define KV1 (64 * SPF)
#define KVSZ (4 * KV1)
#define QOFF (2 * QSZ)
#define FL_SMEM ((QOFF + 2 * KVSZ) * 2)     // 110592 B

__global__ void __launch_bounds__(256)
flash2(float* __restrict__ ent_out)
{
    extern __shared__ __nv_bfloat16 sf[];
    const uint32_t sbase = smem_u32(sf);

    const int qt = blockIdx.x, bh = blockIdx.y;
    const int b = bh >> 4, h = bh & 15;
    const int qg0 = qt << 7;
    const int tid = threadIdx.x, wid = tid >> 5, lane = tid & 31;
    const size_t hb = (size_t)b * Nseq * Dmod + (size_t)h * DHd;

    // Q tile: 2 arrays x 128 rows, one row per thread, 8x16B cp.async
    {
        const int arr = tid >> 7, row = tid & 127;
        const __nv_bfloat16* src = (arr ? g_ql : g_qh) + hb + (size_t)(qg0 + row) * Dmod;
        uint32_t dst = sbase + (uint32_t)(arr * QSZ + row * SPF) * 2;
#pragma unroll
        for (int j = 0; j < 8; j++) CP_ASYNC16(dst + j * 16, src + j * 8);
    }

    auto loadkv = [&](int kt) {
        const int st = kt & 1;
        const int arr = tid >> 6, row = tid & 63;
        const __nv_bfloat16* src =
            (arr == 0) ? g_kh : (arr == 1) ? g_kl : (arr == 2) ? g_vh : g_vl;
        src += hb + (size_t)(kt * 64 + row) * Dmod;
        uint32_t dst = sbase + (uint32_t)(QOFF + st * KVSZ + arr * KV1 + row * SPF) * 2;
#pragma unroll
        for (int j = 0; j < 8; j++) CP_ASYNC16(dst + j * 16, src + j * 8);
    };

    // fragment lane offsets (bytes)
    const uint32_t a_off = (uint32_t)(((wid << 4) + (lane & 15)) * SPF + ((lane >> 4) << 3)) * 2;
    const uint32_t b_off = (uint32_t)(((((lane >> 3) & 1) << 3) + (lane & 7)) * SPF + ((lane >> 4) << 3)) * 2;
    const uint32_t v_off = (uint32_t)(((lane & 7) + ((lane >> 4) << 3)) * SPF + (((lane >> 3) & 1) << 3)) * 2;

    float oacc[8][4];
#pragma unroll
    for (int f = 0; f < 8; f++)
#pragma unroll
        for (int c = 0; c < 4; c++) oacc[f][c] = 0.f;
    float m0 = -1e30f, m1 = -1e30f, l0 = 0.f, l1 = 0.f, E0 = 0.f, E1 = 0.f;

    const int row0 = qg0 + (wid << 4) + (lane >> 2);   // global q row (lo)
    const int ktiles = 2 * qt + 2;

    loadkv(0); CP_COMMIT();

    for (int kt = 0; kt < ktiles; kt++) {
        if (kt + 1 < ktiles) { loadkv(kt + 1); CP_COMMIT(); CP_WAIT1(); }
        else CP_WAIT0();
        __syncthreads();

        const uint32_t stk = sbase + (uint32_t)(QOFF + (kt & 1) * KVSZ) * 2;
        const uint32_t qh_s = sbase, ql_s = sbase + QSZ * 2;
        const uint32_t kh_s = stk, kl_s = stk + KV1 * 2;
        const uint32_t vh_s = stk + 2 * KV1 * 2, vl_s = stk + 3 * KV1 * 2;

        // ---- S = Q K^T : 3 split passes, Q frags loaded once per kc ----
        float sfr[8][4];
#pragma unroll
        for (int f = 0; f < 8; f++)
#pragma unroll
            for (int c = 0; c < 4; c++) sfr[f][c] = 0.f;

#pragma unroll
        for (int kc = 0; kc < 4; kc++) {
            uint32_t aH[4], aL[4];
            LDSM4(aH[0], aH[1], aH[2], aH[3], qh_s + a_off + kc * 32);
            LDSM4(aL[0], aL[1], aL[2], aL[3], ql_s + a_off + kc * 32);
#pragma unroll
            for (int g = 0; g < 4; g++) {
                uint32_t h0, h1, h2, h3, e0, e1, e2, e3;
                LDSM4(h0, h1, h2, h3, kh_s + b_off + g * (16 * SPF * 2) + kc * 32);
                LDSM4(e0, e1, e2, e3, kl_s + b_off + g * (16 * SPF * 2) + kc * 32);
                MMAS(sfr[2 * g],     aH[0], aH[1], aH[2], aH[3], h0, h2);
                MMAS(sfr[2 * g + 1], aH[0], aH[1], aH[2], aH[3], h1, h3);
                MMAS(sfr[2 * g],     aL[0], aL[1], aL[2], aL[3], h0, h2);
                MMAS(sfr[2 * g + 1], aL[0], aL[1], aL[2], aL[3], h1, h3);
                MMAS(sfr[2 * g],     aH[0], aH[1], aH[2], aH[3], e0, e2);
                MMAS(sfr[2 * g + 1], aH[0], aH[1], aH[2], aH[3], e1, e3);
            }
        }

        // ---- causal mask (only tiles that can cross the diagonal) ----
        const int k0g = kt << 6;
        if (k0g + 63 > qg0 + (wid << 4)) {
#pragma unroll
            for (int f = 0; f < 8; f++) {
                const int col = k0g + 8 * f + ((lane & 3) << 1);
                if (col     > row0)     sfr[f][0] = -1e30f;
                if (col + 1 > row0)     sfr[f][1] = -1e30f;
                if (col     > row0 + 8) sfr[f][2] = -1e30f;
                if (col + 1 > row0 + 8) sfr[f][3] = -1e30f;
            }
        }

        // ---- online softmax + entropy state ----
        float mt0 = -1e30f, mt1 = -1e30f;
#pragma unroll
        for (int f = 0; f < 8; f++) {
            mt0 = fmaxf(mt0, fmaxf(sfr[f][0], sfr[f][1]));
            mt1 = fmaxf(mt1, fmaxf(sfr[f][2], sfr[f][3]));
        }
        mt0 = fmaxf(mt0, __shfl_xor_sync(0xffffffffu, mt0, 1));
        mt0 = fmaxf(mt0, __shfl_xor_sync(0xffffffffu, mt0, 2));
        mt1 = fmaxf(mt1, __shfl_xor_sync(0xffffffffu, mt1, 1));
        mt1 = fmaxf(mt1, __shfl_xor_sync(0xffffffffu, mt1, 2));
        const float m0n = fmaxf(m0, mt0), m1n = fmaxf(m1, mt1);
        const float sc0 = __expf(m0 - m0n), sc1 = __expf(m1 - m1n);
        E0 = sc0 * (E0 + (m0 - m0n) * l0);
        E1 = sc1 * (E1 + (m1 - m1n) * l1);
        l0 *= sc0; l1 *= sc1;
        m0 = m0n; m1 = m1n;

        uint32_t ph[8][2], pl[8][2];
#pragma unroll
        for (int f = 0; f < 8; f++) {
            float s00 = sfr[f][0] - m0, s01 = sfr[f][1] - m0;
            float s10 = sfr[f][2] - m1, s11 = sfr[f][3] - m1;
            float e00 = __expf(s00), e01 = __expf(s01);
            float e10 = __expf(s10), e11 = __expf(s11);
            l0 += e00 + e01; l1 += e10 + e11;
            E0 += e00 * s00 + e01 * s01;
            E1 += e10 * s10 + e11 * s11;
            uint32_t hp0 = pack_bf2(e00, e01);
            uint32_t hp1 = pack_bf2(e10, e11);
            ph[f][0] = hp0; ph[f][1] = hp1;
            __nv_bfloat162 t0 = *(__nv_bfloat162*)&hp0;
            __nv_bfloat162 t1 = *(__nv_bfloat162*)&hp1;
            pl[f][0] = pack_bf2(e00 - __bfloat162float(t0.x), e01 - __bfloat162float(t0.y));
            pl[f][1] = pack_bf2(e10 - __bfloat162float(t1.x), e11 - __bfloat162float(t1.y));
            oacc[f][0] *= sc0; oacc[f][1] *= sc0;
            oacc[f][2] *= sc1; oacc[f][3] *= sc1;
        }

        // ---- O += P V : 3 split passes, V frags loaded once per (kc,dg) ----
#pragma unroll
        for (int kc = 0; kc < 4; kc++) {
            const uint32_t pH0 = ph[2 * kc][0], pH1 = ph[2 * kc][1];
            const uint32_t pH2 = ph[2 * kc + 1][0], pH3 = ph[2 * kc + 1][1];
            const uint32_t pL0 = pl[2 * kc][0], pL1 = pl[2 * kc][1];
            const uint32_t pL2 = pl[2 * kc + 1][0], pL3 = pl[2 * kc + 1][1];
#pragma unroll
            for (int dg = 0; dg < 4; dg++) {
                uint32_t w0, w1, w2, w3, y0, y1, y2, y3;
                LDSM4T(w0, w1, w2, w3, vh_s + v_off + kc * (16 * SPF * 2) + dg * 32);
                LDSM4T(y0, y1, y2, y3, vl_s + v_off + kc * (16 * SPF * 2) + dg * 32);
                MMAS(oacc[2 * dg],     pH0, pH1, pH2, pH3, w0, w2);
                MMAS(oacc[2 * dg + 1], pH0, pH1, pH2, pH3, w1, w3);
                MMAS(oacc[2 * dg],     pL0, pL1, pL2, pL3, w0, w2);
                MMAS(oacc[2 * dg + 1], pL0, pL1, pL2, pL3, w1, w3);
                MMAS(oacc[2 * dg],     pH0, pH1, pH2, pH3, y0, y2);
                MMAS(oacc[2 * dg + 1], pH0, pH1, pH2, pH3, y1, y3);
            }
        }
        __syncthreads();
    }

    // ---- final 4-lane row reductions ----
    l0 += __shfl_xor_sync(0xffffffffu, l0, 1); l0 += __shfl_xor_sync(0xffffffffu, l0, 2);
    l1 += __shfl_xor_sync(0xffffffffu, l1, 1); l1 += __shfl_xor_sync(0xffffffffu, l1, 2);
    E0 += __shfl_xor_sync(0xffffffffu, E0, 1); E0 += __shfl_xor_sync(0xffffffffu, E0, 2);
    E1 += __shfl_xor_sync(0xffffffffu, E1, 1); E1 += __shfl_xor_sync(0xffffffffu, E1, 2);

    const float inv0 = 1.f / l0, inv1 = 1.f / l1;
    const float f0 = inv0 * g_gate[b * Nseq + row0];
    const float f1 = inv1 * g_gate[b * Nseq + row0 + 8];

    if ((lane & 3) == 0) {
        ent_out[bh * Nseq + row0]     = __logf(l0) - E0 * inv0 - (float)(row0 + 1) * 1e-6f;
        ent_out[bh * Nseq + row0 + 8] = __logf(l1) - E1 * inv1 - (float)(row0 + 9) * 1e-6f;
    }

    float* op0 = g_AT + hb + (size_t)row0 * Dmod;
    float* op1 = g_AT + hb + (size_t)(row0 + 8) * Dmod;
    const int dc = (lane & 3) << 1;
#pragma unroll
    for (int f = 0; f < 8; f++) {
        *(float2*)(op0 + 8 * f + dc) = make_float2(oacc[f][0] * f0, oacc[f][1] * f0);
        *(float2*)(op1 + 8 * f + dc) = make_float2(oacc[f][2] * f1, oacc[f][3] * f1);
    }
}

// ---------------------------------------------------------------------------
extern "C" void kernel_launch(void* const* d_in, const int* in_sizes, int n_in,
                              void* d_out, int out_size)
{
    const float* x   = (const float*)d_in[0];
    // d_in[1] = attn_bias (causal prior handled analytically by loop bounds)
    const float* Wq  = (const float*)d_in[2];
    const float* bq  = (const float*)d_in[3];
    const float* Wk  = (const float*)d_in[4];
    const float* bk  = (const float*)d_in[5];
    const float* Wv  = (const float*)d_in[6];
    const float* bv  = (const float*)d_in[7];
    const float* Wg1 = (const float*)d_in[8];
    const float* bg1 = (const float*)d_in[9];
    const float* Wg2 = (const float*)d_in[10];
    const float* bg2 = (const float*)d_in[11];
    const float* Wo  = (const float*)d_in[12];
    const float* bo  = (const float*)d_in[13];

    float* out = (float*)d_out;

    float *Qp, *Kp, *Vp, *H1p, *ATp, *gp;
    __nv_bfloat16 *xh, *xl, *ah, *al, *Whp, *Wlp;
    __nv_bfloat16 *qh, *ql, *kh, *kl, *vh, *vl;
    cudaGetSymbolAddress((void**)&Qp,  g_Q);
    cudaGetSymbolAddress((void**)&Kp,  g_K);
    cudaGetSymbolAddress((void**)&Vp,  g_V);
    cudaGetSymbolAddress((void**)&H1p, g_H1);
    cudaGetSymbolAddress((void**)&ATp, g_AT);
    cudaGetSymbolAddress((void**)&gp,  g_gate);
    cudaGetSymbolAddress((void**)&xh,  g_xhi);
    cudaGetSymbolAddress((void**)&xl,  g_xlo);
    cudaGetSymbolAddress((void**)&ah,  g_ahi);
    cudaGetSymbolAddress((void**)&al,  g_alo);
    cudaGetSymbolAddress((void**)&Whp, g_Wh);
    cudaGetSymbolAddress((void**)&Wlp, g_Wl);
    cudaGetSymbolAddress((void**)&qh,  g_qh);
    cudaGetSymbolAddress((void**)&ql,  g_ql);
    cudaGetSymbolAddress((void**)&kh,  g_kh);
    cudaGetSymbolAddress((void**)&kl,  g_kl);
    cudaGetSymbolAddress((void**)&vh,  g_vh);
    cudaGetSymbolAddress((void**)&vl,  g_vl);

    const size_t WSZ = (size_t)Dmod * Dmod;

    cudaFuncSetAttribute(flash2, cudaFuncAttributeMaxDynamicSharedMemorySize, FL_SMEM);

    // weight transpose + split: slots 0..4 = Wq,Wk,Wv,Wg1,Wo
    dim3 wtg(32, 32);
    wsplit<<<wtg, 256>>>(Wq,  Whp + 0 * WSZ, Wlp + 0 * WSZ);
    wsplit<<<wtg, 256>>>(Wk,  Whp + 1 * WSZ, Wlp + 1 * WSZ);
    wsplit<<<wtg, 256>>>(Wv,  Whp + 2 * WSZ, Wlp + 2 * WSZ);
    wsplit<<<wtg, 256>>>(Wg1, Whp + 3 * WSZ, Wlp + 3 * WSZ);
    wsplit<<<wtg, 256>>>(Wo,  Whp + 4 * WSZ, Wlp + 4 * WSZ);

    ssplit<<<OUT_ELEMS / 1024, 256>>>(x, xh, xl, 1.0f);

    // fused Q/K/V/G1 projections (GELU on seg 3)
    mma_gemm<<<dim3(8, 24, 4), 256>>>(
        xh, xl,
        Whp + 0 * WSZ, Wlp + 0 * WSZ, Whp + 1 * WSZ, Wlp + 1 * WSZ,
        Whp + 2 * WSZ, Wlp + 2 * WSZ, Whp + 3 * WSZ, Wlp + 3 * WSZ,
        bq, bk, bv, bg1,
        Qp, Kp, Vp, H1p, 3);

    // split Q (pre-scaled), K, V for flash
    ssplit<<<OUT_ELEMS / 1024, 256>>>(Qp, qh, ql, SCALE);
    ssplit<<<OUT_ELEMS / 1024, 256>>>(Kp, kh, kl, 1.0f);
    ssplit<<<OUT_ELEMS / 1024, 256>>>(Vp, vh, vl, 1.0f);

    gate_kernel<<<ROWS, 256>>>(H1p, Wg2, bg2, gp);

    flash2<<<dim3(Nseq / 128, BH), 256, FL_SMEM>>>(out + OUT_ELEMS);

    // output projection
    ssplit<<<OUT_ELEMS / 1024, 256>>>(ATp, ah, al, 1.0f);
    mma_gemm<<<dim3(8, 24, 1), 256>>>(
        ah, al,
        Whp + 4 * WSZ, Wlp + 4 * WSZ, Whp + 4 * WSZ, Wlp + 4 * WSZ,
        Whp + 4 * WSZ, Wlp + 4 * WSZ, Whp + 4 * WSZ, Wlp + 4 * WSZ,
        bo, bo, bo, bo,
        out, out, out, out, -1);
}

// round 10
// speedup vs baseline: 8.8978x; 1.0499x over previous
#include <cuda_runtime.h>
#include <cuda_bf16.h>
#include <math.h>
#include <stdint.h>

#define Bdim 2
#define Nseq 1536
#define Dmod 1024
#define Hn   16
#define DHd  64
#define SCALE 0.125f
#define ROWS (Bdim * Nseq)               // 3072
#define OUT_ELEMS ((size_t)ROWS * Dmod)  // 3145728
#define BH (Bdim * Hn)                   // 32

// ---------------------------------------------------------------------------
// scratch (no cudaMalloc allowed)
// ---------------------------------------------------------------------------
__device__ float g_H1[ROWS * Dmod];
__device__ float g_gate[ROWS];

// bf16 split operands
__device__ __nv_bfloat16 g_xhi[ROWS * Dmod];
__device__ __nv_bfloat16 g_xlo[ROWS * Dmod];
__device__ __nv_bfloat16 g_ahi[ROWS * Dmod];   // flash output, hi
__device__ __nv_bfloat16 g_alo[ROWS * Dmod];   // flash output, lo
__device__ __nv_bfloat16 g_Wh[5 * Dmod * Dmod];   // transposed K-major, hi
__device__ __nv_bfloat16 g_Wl[5 * Dmod * Dmod];   // transposed K-major, lo
// flash operands (bf16 hi/lo of Q*SCALE, K, V) — written by mma_gemm epilogue
__device__ __nv_bfloat16 g_qh[ROWS * Dmod];
__device__ __nv_bfloat16 g_ql[ROWS * Dmod];
__device__ __nv_bfloat16 g_kh[ROWS * Dmod];
__device__ __nv_bfloat16 g_kl[ROWS * Dmod];
__device__ __nv_bfloat16 g_vh[ROWS * Dmod];
__device__ __nv_bfloat16 g_vl[ROWS * Dmod];

// ---------------------------------------------------------------------------
// baseline-ISA helpers
// ---------------------------------------------------------------------------
__device__ __forceinline__ uint32_t smem_u32(const void* p) {
    uint32_t a;
    asm("{ .reg .u64 t; cvta.to.shared.u64 t, %1; cvt.u32.u64 %0, t; }"
        : "=r"(a) : "l"(p));
    return a;
}

#define LDSM4(r0, r1, r2, r3, a)                                              \
    asm volatile("ldmatrix.sync.aligned.m8n8.x4.shared.b16 {%0,%1,%2,%3}, [%4];" \
                 : "=r"(r0), "=r"(r1), "=r"(r2), "=r"(r3) : "r"(a))
#define LDSM4T(r0, r1, r2, r3, a)                                             \
    asm volatile("ldmatrix.sync.aligned.m8n8.x4.trans.shared.b16 {%0,%1,%2,%3}, [%4];" \
                 : "=r"(r0), "=r"(r1), "=r"(r2), "=r"(r3) : "r"(a))

#define MMA16816(d, a, b)                                                     \
    asm volatile("mma.sync.aligned.m16n8k16.row.col.f32.bf16.bf16.f32 "       \
                 "{%0,%1,%2,%3}, {%4,%5,%6,%7}, {%8,%9}, {%0,%1,%2,%3};"      \
                 : "+f"((d)[0]), "+f"((d)[1]), "+f"((d)[2]), "+f"((d)[3])     \
                 : "r"((a)[0]), "r"((a)[1]), "r"((a)[2]), "r"((a)[3]),        \
                   "r"((b)[0]), "r"((b)[1]))

#define MMAS(d, a0_, a1_, a2_, a3_, b0_, b1_)                                 \
    asm volatile("mma.sync.aligned.m16n8k16.row.col.f32.bf16.bf16.f32 "       \
                 "{%0,%1,%2,%3}, {%4,%5,%6,%7}, {%8,%9}, {%0,%1,%2,%3};"      \
                 : "+f"((d)[0]), "+f"((d)[1]), "+f"((d)[2]), "+f"((d)[3])     \
                 : "r"(a0_), "r"(a1_), "r"(a2_), "r"(a3_), "r"(b0_), "r"(b1_))

#define CP_ASYNC16(dst, src)                                                  \
    asm volatile("cp.async.cg.shared.global [%0], [%1], 16;"                  \
                 :: "r"(dst), "l"(src))
#define CP_COMMIT() asm volatile("cp.async.commit_group;" ::: "memory")
#define CP_WAIT1()  asm volatile("cp.async.wait_group 1;" ::: "memory")
#define CP_WAIT0()  asm volatile("cp.async.wait_group 0;" ::: "memory")

// pack two f32 -> bf16x2 register (arg order: lo first)
__device__ __forceinline__ uint32_t pack_bf2(float lo, float hi) {
    uint32_t r;
    asm("cvt.rn.bf16x2.f32 %0, %1, %2;" : "=r"(r) : "f"(hi), "f"(lo));
    return r;
}

// split one fp32 value into bf16 hi + lo
__device__ __forceinline__ void split1(float v, __nv_bfloat16& h, __nv_bfloat16& l) {
    h = __float2bfloat16(v);
    l = __float2bfloat16(v - __bfloat162float(h));
}

// ---------------------------------------------------------------------------
// split fp32 -> bf16 hi/lo with scale (vectorized x4) — used for x only
// ---------------------------------------------------------------------------
__global__ void __launch_bounds__(256)
ssplit(const float* __restrict__ A, __nv_bfloat16* __restrict__ H,
       __nv_bfloat16* __restrict__ L, float sc)
{
    int i = blockIdx.x * 256 + threadIdx.x;
    float4 v = ((const float4*)A)[i];
    float f[4] = {v.x * sc, v.y * sc, v.z * sc, v.w * sc};
    __nv_bfloat16 h[4], l[4];
#pragma unroll
    for (int j = 0; j < 4; j++) split1(f[j], h[j], l[j]);
    ((__nv_bfloat162*)H)[2 * i]     = __nv_bfloat162(h[0], h[1]);
    ((__nv_bfloat162*)H)[2 * i + 1] = __nv_bfloat162(h[2], h[3]);
    ((__nv_bfloat162*)L)[2 * i]     = __nv_bfloat162(l[0], l[1]);
    ((__nv_bfloat162*)L)[2 * i + 1] = __nv_bfloat162(l[2], l[3]);
}

// ---------------------------------------------------------------------------
// transpose + split: WT[n][k] = W[k][n] -> bf16 hi/lo
// ---------------------------------------------------------------------------
__global__ void __launch_bounds__(256)
wsplit(const float* __restrict__ W, __nv_bfloat16* __restrict__ Th,
       __nv_bfloat16* __restrict__ Tl)
{
    __shared__ float t[32][33];
    const int n0 = blockIdx.x << 5, k0 = blockIdx.y << 5;
    const int tx = threadIdx.x & 31, ty = threadIdx.x >> 5;  // 32x8
#pragma unroll
    for (int j = 0; j < 32; j += 8)
        t[ty + j][tx] = W[(size_t)(k0 + ty + j) * Dmod + n0 + tx];
    __syncthreads();
#pragma unroll
    for (int j = 0; j < 32; j += 8) {
        float v = t[tx][ty + j];
        __nv_bfloat16 h, l;
        split1(v, h, l);
        size_t o = (size_t)(n0 + ty + j) * Dmod + k0 + tx;
        Th[o] = h;
        Tl[o] = l;
    }
}

// ---------------------------------------------------------------------------
// mma.sync split-bf16 GEMM: C = A @ W + bias, 128x128 tiles.
// mode 1 (QKVG1): segs 0..2 write bf16 hi/lo pairs (seg0 scaled by SCALE),
//                 seg 3 writes fp32 with exact GELU.
// mode 0 (outproj): seg 0 writes fp32 C0.
// ---------------------------------------------------------------------------
#define SPAD 40
#define NCH  96

__global__ void __launch_bounds__(256)
mma_gemm(const __nv_bfloat16* __restrict__ Ahi, const __nv_bfloat16* __restrict__ Alo,
         const __nv_bfloat16* __restrict__ W0h, const __nv_bfloat16* __restrict__ W0l,
         const __nv_bfloat16* __restrict__ W1h, const __nv_bfloat16* __restrict__ W1l,
         const __nv_bfloat16* __restrict__ W2h, const __nv_bfloat16* __restrict__ W2l,
         const __nv_bfloat16* __restrict__ W3h, const __nv_bfloat16* __restrict__ W3l,
         const float* __restrict__ b0, const float* __restrict__ b1,
         const float* __restrict__ b2, const float* __restrict__ b3,
         float* __restrict__ C0,
         __nv_bfloat16* __restrict__ H0, __nv_bfloat16* __restrict__ L0,
         __nv_bfloat16* __restrict__ H1o, __nv_bfloat16* __restrict__ L1o,
         __nv_bfloat16* __restrict__ H2, __nv_bfloat16* __restrict__ L2,
         float* __restrict__ C3, int mode)
{
    __shared__ __nv_bfloat16 As[2][128 * SPAD];
    __shared__ __nv_bfloat16 Bs[2][128 * SPAD];

    const int tid = threadIdx.x, wid = tid >> 5, lane = tid & 31;
    const int n0 = blockIdx.x << 7, m0 = blockIdx.y << 7;
    const int seg = blockIdx.z;
    const __nv_bfloat16* Wh = seg == 0 ? W0h : seg == 1 ? W1h : seg == 2 ? W2h : W3h;
    const __nv_bfloat16* Wl = seg == 0 ? W0l : seg == 1 ? W1l : seg == 2 ? W2l : W3l;
    const float* Bp = seg == 0 ? b0 : seg == 1 ? b1 : seg == 2 ? b2 : b3;

    const int wm = (wid & 1) << 6;
    const int wn = (wid >> 1) << 5;

    float acc[4][4][4];
#pragma unroll
    for (int i = 0; i < 4; i++)
#pragma unroll
        for (int j = 0; j < 4; j++)
#pragma unroll
            for (int c = 0; c < 4; c++) acc[i][j][c] = 0.f;

    const int lrow = tid >> 1;
    const int lch  = (tid & 1) << 1;

    auto load = [&](int s) {
        const int st = s & 1;
        const int p = s >> 5, k0 = (s & 31) << 5;
        const __nv_bfloat16* Ag = ((p < 2) ? Ahi : Alo) + (size_t)(m0 + lrow) * Dmod + k0;
        const __nv_bfloat16* Bg = ((p == 1) ? Wl : Wh)  + (size_t)(n0 + lrow) * Dmod + k0;
        uint32_t sa = smem_u32(&As[st][lrow * SPAD]);
        uint32_t sb = smem_u32(&Bs[st][lrow * SPAD]);
#pragma unroll
        for (int c = 0; c < 2; c++) {
            CP_ASYNC16(sa + (lch + c) * 16, Ag + (lch + c) * 8);
            CP_ASYNC16(sb + (lch + c) * 16, Bg + (lch + c) * 8);
        }
    };

    const uint32_t a_off = (uint32_t)((wm + (lane & 15)) * SPAD + (lane >> 4) * 8) * 2;
    const uint32_t b_off = (uint32_t)((wn + ((lane >> 3) & 1) * 8 + (lane & 7)) * SPAD
                                      + (lane >> 4) * 8) * 2;

    load(0); CP_COMMIT();

    for (int s = 0; s < NCH; s++) {
        if (s + 1 < NCH) { load(s + 1); CP_COMMIT(); CP_WAIT1(); }
        else CP_WAIT0();
        __syncthreads();

        const uint32_t ab = smem_u32(As[s & 1]) + a_off;
        const uint32_t bb = smem_u32(Bs[s & 1]) + b_off;

#pragma unroll
        for (int kh = 0; kh < 2; kh++) {
            uint32_t af[4][4], bf[4][2];
#pragma unroll
            for (int mi = 0; mi < 4; mi++)
                LDSM4(af[mi][0], af[mi][1], af[mi][2], af[mi][3],
                      ab + mi * 16 * SPAD * 2 + kh * 32);
#pragma unroll
            for (int nq = 0; nq < 2; nq++)
                LDSM4(bf[2 * nq][0], bf[2 * nq + 1][0],
                      bf[2 * nq][1], bf[2 * nq + 1][1],
                      bb + nq * 16 * SPAD * 2 + kh * 32);
#pragma unroll
            for (int mi = 0; mi < 4; mi++)
#pragma unroll
                for (int nj = 0; nj < 4; nj++)
                    MMA16816(acc[mi][nj], af[mi], bf[nj]);
        }
        __syncthreads();
    }

    // ---- epilogue ----
    const int gp = lane >> 2, t4 = lane & 3;
    const bool bfout = (mode == 1) && (seg <= 2);
    __nv_bfloat16* Hd = seg == 0 ? H0 : seg == 1 ? H1o : H2;
    __nv_bfloat16* Ld = seg == 0 ? L0 : seg == 1 ? L1o : L2;
    const float osc = (mode == 1 && seg == 0) ? SCALE : 1.0f;
    const bool act = (mode == 1) && (seg == 3);
    float* Cd = (mode == 1) ? C3 : C0;

#pragma unroll
    for (int mi = 0; mi < 4; mi++) {
#pragma unroll
        for (int nj = 0; nj < 4; nj++) {
            const int col = n0 + wn + nj * 8 + t4 * 2;
            const float bi0 = Bp[col], bi1 = Bp[col + 1];
#pragma unroll
            for (int h = 0; h < 2; h++) {
                const int row = m0 + wm + mi * 16 + gp + h * 8;
                float v0 = acc[mi][nj][2 * h + 0] + bi0;
                float v1 = acc[mi][nj][2 * h + 1] + bi1;
                if (bfout) {
                    v0 *= osc; v1 *= osc;
                    __nv_bfloat16 h0, l0, h1, l1;
                    split1(v0, h0, l0);
                    split1(v1, h1, l1);
                    *(__nv_bfloat162*)(Hd + (size_t)row * Dmod + col) = __nv_bfloat162(h0, h1);
                    *(__nv_bfloat162*)(Ld + (size_t)row * Dmod + col) = __nv_bfloat162(l0, l1);
                } else {
                    if (act) {
                        v0 = 0.5f * v0 * (1.0f + erff(v0 * 0.70710678118654752f));
                        v1 = 0.5f * v1 * (1.0f + erff(v1 * 0.70710678118654752f));
                    }
                    *(float2*)(Cd + (size_t)row * Dmod + col) = make_float2(v0, v1);
                }
            }
        }
    }
}

// ---------------------------------------------------------------------------
// gate[row] = sigmoid(dot(H1[row,:], Wg2) + bg2)
// ---------------------------------------------------------------------------
__global__ void __launch_bounds__(256)
gate_kernel(const float* __restrict__ H1,
            const float* __restrict__ Wg2,
            const float* __restrict__ bg2,
            float* __restrict__ gate)
{
    __shared__ float red[8];
    const int row = blockIdx.x;
    const float* hp = H1 + (size_t)row * Dmod;
    float loc = 0.f;
    for (int k = threadIdx.x; k < Dmod; k += blockDim.x)
        loc += hp[k] * Wg2[k];
#pragma unroll
    for (int o = 16; o > 0; o >>= 1)
        loc += __shfl_xor_sync(0xffffffffu, loc, o);
    if ((threadIdx.x & 31) == 0) red[threadIdx.x >> 5] = loc;
    __syncthreads();
    if (threadIdx.x == 0) {
        float s = 0.f;
        for (int i = 0; i < 8; i++) s += red[i];
        gate[row] = 1.f / (1.f + __expf(-(s + bg2[0])));
    }
}

// ---------------------------------------------------------------------------
// mma.sync flash attention, online softmax + online entropy.
// CTA = (128-query tile, bh), qt REVERSED so heavy tiles launch first.
// Epilogue writes bf16 hi/lo (g_ahi/g_alo) directly for the out projection.
// ---------------------------------------------------------------------------
#define SPF 72
#define QSZ (128 * SPF)
#define KV1 (64 * SPF)
#define KVSZ (4 * KV1)
#define QOFF (2 * QSZ)
#define FL_SMEM ((QOFF + 2 * KVSZ) * 2)     // 110592 B

__global__ void __launch_bounds__(256)
flash2(float* __restrict__ ent_out)
{
    extern __shared__ __nv_bfloat16 sf[];
    const uint32_t sbase = smem_u32(sf);

    const int qt = (Nseq / 128 - 1) - blockIdx.x;   // heavy tiles first
    const int bh = blockIdx.y;
    const int b = bh >> 4, h = bh & 15;
    const int qg0 = qt << 7;
    const int tid = threadIdx.x, wid = tid >> 5, lane = tid & 31;
    const size_t hb = (size_t)b * Nseq * Dmod + (size_t)h * DHd;

    // Q tile: 2 arrays x 128 rows, one row per thread, 8x16B cp.async
    {
        const int arr = tid >> 7, row = tid & 127;
        const __nv_bfloat16* src = (arr ? g_ql : g_qh) + hb + (size_t)(qg0 + row) * Dmod;
        uint32_t dst = sbase + (uint32_t)(arr * QSZ + row * SPF) * 2;
#pragma unroll
        for (int j = 0; j < 8; j++) CP_ASYNC16(dst + j * 16, src + j * 8);
    }

    auto loadkv = [&](int kt) {
        const int st = kt & 1;
        const int arr = tid >> 6, row = tid & 63;
        const __nv_bfloat16* src =
            (arr == 0) ? g_kh : (arr == 1) ? g_kl : (arr == 2) ? g_vh : g_vl;
        src += hb + (size_t)(kt * 64 + row) * Dmod;
        uint32_t dst = sbase + (uint32_t)(QOFF + st * KVSZ + arr * KV1 + row * SPF) * 2;
#pragma unroll
        for (int j = 0; j < 8; j++) CP_ASYNC16(dst + j * 16, src + j * 8);
    };

    // fragment lane offsets (bytes)
    const uint32_t a_off = (uint32_t)(((wid << 4) + (lane & 15)) * SPF + ((lane >> 4) << 3)) * 2;
    const uint32_t b_off = (uint32_t)(((((lane >> 3) & 1) << 3) + (lane & 7)) * SPF + ((lane >> 4) << 3)) * 2;
    const uint32_t v_off = (uint32_t)(((lane & 7) + ((lane >> 4) << 3)) * SPF + (((lane >> 3) & 1) << 3)) * 2;

    float oacc[8][4];
#pragma unroll
    for (int f = 0; f < 8; f++)
#pragma unroll
        for (int c = 0; c < 4; c++) oacc[f][c] = 0.f;
    float m0 = -1e30f, m1 = -1e30f, l0 = 0.f, l1 = 0.f, E0 = 0.f, E1 = 0.f;

    const int row0 = qg0 + (wid << 4) + (lane >> 2);   // global q row (lo)
    const int ktiles = 2 * qt + 2;

    loadkv(0); CP_COMMIT();

    for (int kt = 0; kt < ktiles; kt++) {
        if (kt + 1 < ktiles) { loadkv(kt + 1); CP_COMMIT(); CP_WAIT1(); }
        else CP_WAIT0();
        __syncthreads();

        const uint32_t stk = sbase + (uint32_t)(QOFF + (kt & 1) * KVSZ) * 2;
        const uint32_t qh_s = sbase, ql_s = sbase + QSZ * 2;
        const uint32_t kh_s = stk, kl_s = stk + KV1 * 2;
        const uint32_t vh_s = stk + 2 * KV1 * 2, vl_s = stk + 3 * KV1 * 2;

        // ---- S = Q K^T : 3 split passes, Q frags loaded once per kc ----
        float sfr[8][4];
#pragma unroll
        for (int f = 0; f < 8; f++)
#pragma unroll
            for (int c = 0; c < 4; c++) sfr[f][c] = 0.f;

#pragma unroll
        for (int kc = 0; kc < 4; kc++) {
            uint32_t aH[4], aL[4];
            LDSM4(aH[0], aH[1], aH[2], aH[3], qh_s + a_off + kc * 32);
            LDSM4(aL[0], aL[1], aL[2], aL[3], ql_s + a_off + kc * 32);
#pragma unroll
            for (int g = 0; g < 4; g++) {
                uint32_t h0, h1, h2, h3, e0, e1, e2, e3;
                LDSM4(h0, h1, h2, h3, kh_s + b_off + g * (16 * SPF * 2) + kc * 32);
                LDSM4(e0, e1, e2, e3, kl_s + b_off + g * (16 * SPF * 2) + kc * 32);
                MMAS(sfr[2 * g],     aH[0], aH[1], aH[2], aH[3], h0, h2);
                MMAS(sfr[2 * g + 1], aH[0], aH[1], aH[2], aH[3], h1, h3);
                MMAS(sfr[2 * g],     aL[0], aL[1], aL[2], aL[3], h0, h2);
                MMAS(sfr[2 * g + 1], aL[0], aL[1], aL[2], aL[3], h1, h3);
                MMAS(sfr[2 * g],     aH[0], aH[1], aH[2], aH[3], e0, e2);
                MMAS(sfr[2 * g + 1], aH[0], aH[1], aH[2], aH[3], e1, e3);
            }
        }

        // ---- causal mask (only tiles that can cross the diagonal) ----
        const int k0g = kt << 6;
        if (k0g + 63 > qg0 + (wid << 4)) {
#pragma unroll
            for (int f = 0; f < 8; f++) {
                const int col = k0g + 8 * f + ((lane & 3) << 1);
                if (col     > row0)     sfr[f][0] = -1e30f;
                if (col + 1 > row0)     sfr[f][1] = -1e30f;
                if (col     > row0 + 8) sfr[f][2] = -1e30f;
                if (col + 1 > row0 + 8) sfr[f][3] = -1e30f;
            }
        }

        // ---- online softmax + entropy state ----
        float mt0 = -1e30f, mt1 = -1e30f;
#pragma unroll
        for (int f = 0; f < 8; f++) {
            mt0 = fmaxf(mt0, fmaxf(sfr[f][0], sfr[f][1]));
            mt1 = fmaxf(mt1, fmaxf(sfr[f][2], sfr[f][3]));
        }
        mt0 = fmaxf(mt0, __shfl_xor_sync(0xffffffffu, mt0, 1));
        mt0 = fmaxf(mt0, __shfl_xor_sync(0xffffffffu, mt0, 2));
        mt1 = fmaxf(mt1, __shfl_xor_sync(0xffffffffu, mt1, 1));
        mt1 = fmaxf(mt1, __shfl_xor_sync(0xffffffffu, mt1, 2));
        const float m0n = fmaxf(m0, mt0), m1n = fmaxf(m1, mt1);
        const float sc0 = __expf(m0 - m0n), sc1 = __expf(m1 - m1n);
        E0 = sc0 * (E0 + (m0 - m0n) * l0);
        E1 = sc1 * (E1 + (m1 - m1n) * l1);
        l0 *= sc0; l1 *= sc1;
        m0 = m0n; m1 = m1n;

        uint32_t ph[8][2], pl[8][2];
#pragma unroll
        for (int f = 0; f < 8; f++) {
            float s00 = sfr[f][0] - m0, s01 = sfr[f][1] - m0;
            float s10 = sfr[f][2] - m1, s11 = sfr[f][3] - m1;
            float e00 = __expf(s00), e01 = __expf(s01);
            float e10 = __expf(s10), e11 = __expf(s11);
            l0 += e00 + e01; l1 += e10 + e11;
            E0 += e00 * s00 + e01 * s01;
            E1 += e10 * s10 + e11 * s11;
            uint32_t hp0 = pack_bf2(e00, e01);
            uint32_t hp1 = pack_bf2(e10, e11);
            ph[f][0] = hp0; ph[f][1] = hp1;
            __nv_bfloat162 t0 = *(__nv_bfloat162*)&hp0;
            __nv_bfloat162 t1 = *(__nv_bfloat162*)&hp1;
            pl[f][0] = pack_bf2(e00 - __bfloat162float(t0.x), e01 - __bfloat162float(t0.y));
            pl[f][1] = pack_bf2(e10 - __bfloat162float(t1.x), e11 - __bfloat162float(t1.y));
            oacc[f][0] *= sc0; oacc[f][1] *= sc0;
            oacc[f][2] *= sc1; oacc[f][3] *= sc1;
        }

        // ---- O += P V : 3 split passes, V frags loaded once per (kc,dg) ----
#pragma unroll
        for (int kc = 0; kc < 4; kc++) {
            const uint32_t pH0 = ph[2 * kc][0], pH1 = ph[2 * kc][1];
            const uint32_t pH2 = ph[2 * kc + 1][0], pH3 = ph[2 * kc + 1][1];
            const uint32_t pL0 = pl[2 * kc][0], pL1 = pl[2 * kc][1];
            const uint32_t pL2 = pl[2 * kc + 1][0], pL3 = pl[2 * kc + 1][1];
#pragma unroll
            for (int dg = 0; dg < 4; dg++) {
                uint32_t w0, w1, w2, w3, y0, y1, y2, y3;
                LDSM4T(w0, w1, w2, w3, vh_s + v_off + kc * (16 * SPF * 2) + dg * 32);
                LDSM4T(y0, y1, y2, y3, vl_s + v_off + kc * (16 * SPF * 2) + dg * 32);
                MMAS(oacc[2 * dg],     pH0, pH1, pH2, pH3, w0, w2);
                MMAS(oacc[2 * dg + 1], pH0, pH1, pH2, pH3, w1, w3);
                MMAS(oacc[2 * dg],     pL0, pL1, pL2, pL3, w0, w2);
                MMAS(oacc[2 * dg + 1], pL0, pL1, pL2, pL3, w1, w3);
                MMAS(oacc[2 * dg],     pH0, pH1, pH2, pH3, y0, y2);
                MMAS(oacc[2 * dg + 1], pH0, pH1, pH2, pH3, y1, y3);
            }
        }
        __syncthreads();
    }

    // ---- final 4-lane row reductions ----
    l0 += __shfl_xor_sync(0xffffffffu, l0, 1); l0 += __shfl_xor_sync(0xffffffffu, l0, 2);
    l1 += __shfl_xor_sync(0xffffffffu, l1, 1); l1 += __shfl_xor_sync(0xffffffffu, l1, 2);
    E0 += __shfl_xor_sync(0xffffffffu, E0, 1); E0 += __shfl_xor_sync(0xffffffffu, E0, 2);
    E1 += __shfl_xor_sync(0xffffffffu, E1, 1); E1 += __shfl_xor_sync(0xffffffffu, E1, 2);

    const float inv0 = 1.f / l0, inv1 = 1.f / l1;
    const float f0 = inv0 * g_gate[b * Nseq + row0];
    const float f1 = inv1 * g_gate[b * Nseq + row0 + 8];

    if ((lane & 3) == 0) {
        ent_out[bh * Nseq + row0]     = __logf(l0) - E0 * inv0 - (float)(row0 + 1) * 1e-6f;
        ent_out[bh * Nseq + row0 + 8] = __logf(l1) - E1 * inv1 - (float)(row0 + 9) * 1e-6f;
    }

    // ---- epilogue: write bf16 hi/lo directly for the out projection ----
    __nv_bfloat16* ah0 = g_ahi + hb + (size_t)row0 * Dmod;
    __nv_bfloat16* al0 = g_alo + hb + (size_t)row0 * Dmod;
    __nv_bfloat16* ah1 = g_ahi + hb + (size_t)(row0 + 8) * Dmod;
    __nv_bfloat16* al1 = g_alo + hb + (size_t)(row0 + 8) * Dmod;
    const int dc = (lane & 3) << 1;
#pragma unroll
    for (int f = 0; f < 8; f++) {
        __nv_bfloat16 h0, q0, h1, q1;
        split1(oacc[f][0] * f0, h0, q0);
        split1(oacc[f][1] * f0, h1, q1);
        *(__nv_bfloat162*)(ah0 + 8 * f + dc) = __nv_bfloat162(h0, h1);
        *(__nv_bfloat162*)(al0 + 8 * f + dc) = __nv_bfloat162(q0, q1);
        split1(oacc[f][2] * f1, h0, q0);
        split1(oacc[f][3] * f1, h1, q1);
        *(__nv_bfloat162*)(ah1 + 8 * f + dc) = __nv_bfloat162(h0, h1);
        *(__nv_bfloat162*)(al1 + 8 * f + dc) = __nv_bfloat162(q0, q1);
    }
}

// ---------------------------------------------------------------------------
extern "C" void kernel_launch(void* const* d_in, const int* in_sizes, int n_in,
                              void* d_out, int out_size)
{
    const float* x   = (const float*)d_in[0];
    // d_in[1] = attn_bias (causal prior handled analytically by loop bounds)
    const float* Wq  = (const float*)d_in[2];
    const float* bq  = (const float*)d_in[3];
    const float* Wk  = (const float*)d_in[4];
    const float* bk  = (const float*)d_in[5];
    const float* Wv  = (const float*)d_in[6];
    const float* bv  = (const float*)d_in[7];
    const float* Wg1 = (const float*)d_in[8];
    const float* bg1 = (const float*)d_in[9];
    const float* Wg2 = (const float*)d_in[10];
    const float* bg2 = (const float*)d_in[11];
    const float* Wo  = (const float*)d_in[12];
    const float* bo  = (const float*)d_in[13];

    float* out = (float*)d_out;

    float *H1p, *gp;
    __nv_bfloat16 *xh, *xl, *ah, *al, *Whp, *Wlp;
    __nv_bfloat16 *qh, *ql, *kh, *kl, *vh, *vl;
    cudaGetSymbolAddress((void**)&H1p, g_H1);
    cudaGetSymbolAddress((void**)&gp,  g_gate);
    cudaGetSymbolAddress((void**)&xh,  g_xhi);
    cudaGetSymbolAddress((void**)&xl,  g_xlo);
    cudaGetSymbolAddress((void**)&ah,  g_ahi);
    cudaGetSymbolAddress((void**)&al,  g_alo);
    cudaGetSymbolAddress((void**)&Whp, g_Wh);
    cudaGetSymbolAddress((void**)&Wlp, g_Wl);
    cudaGetSymbolAddress((void**)&qh,  g_qh);
    cudaGetSymbolAddress((void**)&ql,  g_ql);
    cudaGetSymbolAddress((void**)&kh,  g_kh);
    cudaGetSymbolAddress((void**)&kl,  g_kl);
    cudaGetSymbolAddress((void**)&vh,  g_vh);
    cudaGetSymbolAddress((void**)&vl,  g_vl);

    const size_t WSZ = (size_t)Dmod * Dmod;

    cudaFuncSetAttribute(flash2, cudaFuncAttributeMaxDynamicSharedMemorySize, FL_SMEM);

    // weight transpose + split: slots 0..4 = Wq,Wk,Wv,Wg1,Wo
    dim3 wtg(32, 32);
    wsplit<<<wtg, 256>>>(Wq,  Whp + 0 * WSZ, Wlp + 0 * WSZ);
    wsplit<<<wtg, 256>>>(Wk,  Whp + 1 * WSZ, Wlp + 1 * WSZ);
    wsplit<<<wtg, 256>>>(Wv,  Whp + 2 * WSZ, Wlp + 2 * WSZ);
    wsplit<<<wtg, 256>>>(Wg1, Whp + 3 * WSZ, Wlp + 3 * WSZ);
    wsplit<<<wtg, 256>>>(Wo,  Whp + 4 * WSZ, Wlp + 4 * WSZ);

    ssplit<<<OUT_ELEMS / 1024, 256>>>(x, xh, xl, 1.0f);

    // fused Q/K/V/G1 projections; Q/K/V written as bf16 hi/lo (Q pre-scaled),
    // H1 written fp32 with exact GELU
    mma_gemm<<<dim3(8, 24, 4), 256>>>(
        xh, xl,
        Whp + 0 * WSZ, Wlp + 0 * WSZ, Whp + 1 * WSZ, Wlp + 1 * WSZ,
        Whp + 2 * WSZ, Wlp + 2 * WSZ, Whp + 3 * WSZ, Wlp + 3 * WSZ,
        bq, bk, bv, bg1,
        nullptr,
        qh, ql, kh, kl, vh, vl,
        H1p, 1);

    gate_kernel<<<ROWS, 256>>>(H1p, Wg2, bg2, gp);

    flash2<<<dim3(Nseq / 128, BH), 256, FL_SMEM>>>(out + OUT_ELEMS);

    // output projection (reads g_ahi/g_alo written by flash2)
    mma_gemm<<<dim3(8, 24, 1), 256>>>(
        ah, al,
        Whp + 4 * WSZ, Wlp + 4 * WSZ, Whp + 4 * WSZ, Wlp + 4 * WSZ,
        Whp + 4 * WSZ, Wlp + 4 * WSZ, Whp + 4 * WSZ, Wlp + 4 * WSZ,
        bo, bo, bo, bo,
        out,
        nullptr, nullptr, nullptr, nullptr, nullptr, nullptr,
        nullptr, 0);
}